// round 14
// baseline (speedup 1.0000x reference)
#include <cuda_runtime.h>
#include <cuda_fp16.h>
#include <cstdint>

#define BS_    2
#define SEQ    1024
#define DMODEL 1024
#define NH     16
#define HD     64
#define MM     32
#define ROWS   (BS_*SEQ)

// ---------------- scratch (device globals) ----------------
__device__ __half g_qkv[ROWS*3*DMODEL];
__device__ float g_mem[ROWS*DMODEL];
__device__ float g_hid[ROWS*DMODEL];
__device__ __half g_h1 [ROWS*DMODEL];
__device__ __half g_att[ROWS*DMODEL];
__device__ __half g_h2 [ROWS*DMODEL];
__device__ __half g_ff [ROWS*4*DMODEL];
__device__ __half g_wq[DMODEL*3*DMODEL];
__device__ __half g_wp[DMODEL*DMODEL];
__device__ __half g_wf[DMODEL*4*DMODEL];
__device__ __half g_wo[4*DMODEL*DMODEL];

// ---------------- helpers ----------------
__device__ __forceinline__ uint32_t smem_to_u32(const void* p) {
    uint32_t a;
    asm("{ .reg .u64 t; cvta.to.shared.u64 t, %1; cvt.u32.u64 %0, t; }" : "=r"(a) : "l"(p));
    return a;
}
__device__ __forceinline__ void cp16(uint32_t s, const void* g) {
    asm volatile("cp.async.cg.shared.global [%0], [%1], 16;" :: "r"(s), "l"(g));
}
#define CP_COMMIT() asm volatile("cp.async.commit_group;" ::: "memory")
#define CP_WAIT1()  asm volatile("cp.async.wait_group 1;" ::: "memory")

__device__ __forceinline__ void ldsm4(uint32_t* r, uint32_t addr) {
    asm volatile("ldmatrix.sync.aligned.m8n8.x4.shared.b16 {%0,%1,%2,%3}, [%4];"
        : "=r"(r[0]), "=r"(r[1]), "=r"(r[2]), "=r"(r[3]) : "r"(addr));
}
__device__ __forceinline__ void ldsm2(uint32_t* r, uint32_t addr) {
    asm volatile("ldmatrix.sync.aligned.m8n8.x2.shared.b16 {%0,%1}, [%2];"
        : "=r"(r[0]), "=r"(r[1]) : "r"(addr));
}
__device__ __forceinline__ void ldsm2t(uint32_t* r, uint32_t addr) {
    asm volatile("ldmatrix.sync.aligned.m8n8.x2.trans.shared.b16 {%0,%1}, [%2];"
        : "=r"(r[0]), "=r"(r[1]) : "r"(addr));
}
__device__ __forceinline__ void mma16816(float* d, const uint32_t* a, const uint32_t* b) {
    asm volatile(
      "mma.sync.aligned.m16n8k16.row.col.f32.f16.f16.f32 "
      "{%0,%1,%2,%3}, {%4,%5,%6,%7}, {%8,%9}, {%0,%1,%2,%3};"
      : "+f"(d[0]), "+f"(d[1]), "+f"(d[2]), "+f"(d[3])
      : "r"(a[0]), "r"(a[1]), "r"(a[2]), "r"(a[3]), "r"(b[0]), "r"(b[1]));
}

__device__ __forceinline__ float gelu_new(float x) {
    float x3 = x * x * x;
    float t  = tanhf(0.7978845608028654f * (x + 0.044715f * x3));
    return 0.5f * x * (1.f + t);
}
__device__ __forceinline__ uint32_t pack_h2(float x, float y) {
    __half2 t = __floats2half2_rn(x, y);
    return *reinterpret_cast<uint32_t*>(&t);
}

// ---------------- prep: fused 4x weight-convert + LN -----------------------
__device__ void wconv_body(float* shm,
    const float* __restrict__ W, __half* __restrict__ hi,
    int K, int N, int bx, int by)
{
    float (*s)[33] = (float(*)[33])shm;
    const int tx = threadIdx.x & 31, ty = threadIdx.x >> 5;
    const int n0 = bx * 32, k0 = by * 32;
    #pragma unroll
    for (int i = 0; i < 4; i++)
        s[ty + 8*i][tx] = W[(size_t)(k0 + ty + 8*i) * N + n0 + tx];
    __syncthreads();
    #pragma unroll
    for (int i = 0; i < 4; i++) {
        int n = ty + 8*i;
        hi[(size_t)(n0 + n) * K + k0 + tx] = __float2half(s[tx][n]);
    }
    __syncthreads();
}

__device__ void wconv4_body(float* shm,
    const float* __restrict__ W, __half* __restrict__ hi,
    int K, int N, int bxg, int by)
{
    #pragma unroll
    for (int t = 0; t < 4; t++)
        wconv_body(shm, W, hi, K, N, bxg * 4 + t, by);
}

__device__ void ln_body(float* shm, int row,
    const float* __restrict__ x, const float* __restrict__ g,
    const float* __restrict__ b, __half* __restrict__ y)
{
    const int tid = threadIdx.x;
    float* rs = shm; float* rs2 = shm + 8;
    const float* xr = x + (size_t)row * DMODEL;
    float4 v = *(const float4*)(xr + tid * 4);
    float s  = v.x + v.y + v.z + v.w;
    float s2 = v.x*v.x + v.y*v.y + v.z*v.z + v.w*v.w;
    #pragma unroll
    for (int o = 16; o; o >>= 1) {
        s  += __shfl_xor_sync(0xffffffffu, s,  o);
        s2 += __shfl_xor_sync(0xffffffffu, s2, o);
    }
    const int w = tid >> 5, l = tid & 31;
    if (!l) { rs[w] = s; rs2[w] = s2; }
    __syncthreads();
    s = 0.f; s2 = 0.f;
    #pragma unroll
    for (int i = 0; i < 8; i++) { s += rs[i]; s2 += rs2[i]; }
    const float mean = s * (1.f / DMODEL);
    const float var  = s2 * (1.f / DMODEL) - mean * mean;
    const float rstd = rsqrtf(var + 1e-5f);
    const int c = tid * 4;
    float4 gg = *(const float4*)(g + c);
    float4 bb = *(const float4*)(b + c);
    float4 o;
    o.x = (v.x - mean) * rstd * gg.x + bb.x;
    o.y = (v.y - mean) * rstd * gg.y + bb.y;
    o.z = (v.z - mean) * rstd * gg.z + bb.z;
    o.w = (v.w - mean) * rstd * gg.w + bb.w;
    uint2 hh;
    hh.x = pack_h2(o.x, o.y); hh.y = pack_h2(o.z, o.w);
    *(uint2*)(y + (size_t)row * DMODEL + c) = hh;
}

// blocks: [0,2048) LN1 | wconv4: attnw 768, cprw 256, fcw 1024, pw 1024
__global__ void __launch_bounds__(256) prep_kernel(
    const float* prev, const float* ln1g, const float* ln1b, __half* h1,
    const float* attnw, __half* wq,
    const float* cprw,  __half* wp,
    const float* fcw,   __half* wf,
    const float* pw,    __half* wo)
{
    __shared__ float shm[32*33];
    int idx = blockIdx.x;
    if (idx < 2048) { ln_body(shm, idx, prev, ln1g, ln1b, h1); return; }
    idx -= 2048;
    if (idx < 768)  { wconv4_body(shm, attnw, wq, 1024, 3072, idx % 24, idx / 24); return; }
    idx -= 768;
    if (idx < 256)  { wconv4_body(shm, cprw, wp, 1024, 1024, idx % 8, idx / 8); return; }
    idx -= 256;
    if (idx < 1024) { wconv4_body(shm, fcw, wf, 1024, 4096, idx % 32, idx / 32); return; }
    idx -= 1024;
    wconv4_body(shm, pw, wo, 4096, 1024, idx % 8, idx / 8);
}

// ---------------- epilogue (shared) -----------------------------------------
template<int EPI>
__device__ __forceinline__ void gemm_epilogue_elem(
    float v0, float v1, const float2 bb, size_t o,
    float* Cf, __half* Ch,
    const float* aux1, const float* aux2, float g)
{
    v0 += bb.x; v1 += bb.y;
    if (EPI == 1) {
        float2 a1 = *(const float2*)(aux1 + o);
        float2 a2 = *(const float2*)(aux2 + o);
        v0 = (1.f - g) * v0 + g * a1.x + a2.x;
        v1 = (1.f - g) * v1 + g * a1.y + a2.y;
    }
    if (EPI == 3) {
        float2 a1 = *(const float2*)(aux1 + o);
        v0 += a1.x; v1 += a1.y;
    }
    if (EPI == 2) {
        v0 = gelu_new(v0); v1 = gelu_new(v1);
        *(uint32_t*)(Ch + o) = pack_h2(v0, v1);
    } else if (EPI == 4) {
        *(uint32_t*)(Ch + o) = pack_h2(v0, v1);
    } else {
        *(float2*)(Cf + o) = make_float2(v0, v1);
    }
}

// ---------------- GEMM 128x128 tile, fp16, K-chunk 64 ------------------------
#define AB_     8192
#define GSTAGE  (4*AB_)                 // 32768
#define GEMM_SMEM (3*GSTAGE)            // 98304

template<int EPI>
__global__ void __launch_bounds__(256, 2) gemm_mma_kernel(
    const __half* __restrict__ A, const __half* __restrict__ B,
    const float* __restrict__ bias,
    float* __restrict__ Cf, __half* __restrict__ Ch,
    int M, int N, int K,
    const float* __restrict__ aux1, const float* __restrict__ aux2,
    const float* __restrict__ gp)
{
    extern __shared__ char smp[];
    const uint32_t sb = smem_to_u32(smp);
    const int tid = threadIdx.x;
    const int wid = tid >> 5, lane = tid & 31;
    const int wm = wid & 1, wn = wid >> 1;
    const int bm = blockIdx.y, bn = blockIdx.x;
    const int NC = K >> 6;

    const size_t Abase = (size_t)bm * 128 * K;
    const size_t Bbase = (size_t)bn * 128 * K;

    float acc[4][4][4];
    #pragma unroll
    for (int i = 0; i < 4; i++)
        #pragma unroll
        for (int j = 0; j < 4; j++)
            #pragma unroll
            for (int x = 0; x < 4; x++) acc[i][j][x] = 0.f;

    const int crow = tid >> 2;
    const int cq   = tid & 3;
    const uint32_t so0 = (uint32_t)(crow * 64 + ((cq ^ (crow & 3)) << 4));
    const uint32_t so1 = so0 + 64 * 64;

    auto issue = [&](int buf, int kt) {
        const int k0 = kt << 6;
        const uint32_t sbase = sb + buf * GSTAGE;
        const size_t g0 = (size_t)crow * K + k0 + cq * 8;
        const size_t g1 = g0 + (size_t)64 * K;
        #pragma unroll
        for (int sl = 0; sl < 2; sl++) {
            cp16(sbase + sl*AB_ + so0,          A + Abase + g0 + sl*32);
            cp16(sbase + sl*AB_ + so1,          A + Abase + g1 + sl*32);
            cp16(sbase + (2+sl)*AB_ + so0,      B + Bbase + g0 + sl*32);
            cp16(sbase + (2+sl)*AB_ + so1,      B + Bbase + g1 + sl*32);
        }
    };

    issue(0, 0); CP_COMMIT();
    issue(1, 1); CP_COMMIT();

    const uint32_t rowA = (uint32_t)(wm * 64 + (lane & 15));
    const uint32_t qa   = (uint32_t)(lane >> 4);
    const uint32_t r3a  = rowA & 3;
    const uint32_t aBase = rowA * 64;
    const uint32_t rowB = (uint32_t)(wn * 32 + (lane & 7));
    const uint32_t qb   = (uint32_t)((lane >> 3) & 1);
    const uint32_t r3b  = rowB & 3;
    const uint32_t bBase = rowB * 64;

    int buf = 0;
    for (int c = 0; c < NC; c++) {
        CP_WAIT1();
        __syncthreads();
        if (c + 2 < NC) { int nb = buf + 2; if (nb >= 3) nb -= 3; issue(nb, c + 2); }
        CP_COMMIT();

        const uint32_t s0 = sb + buf * GSTAGE;
        #pragma unroll
        for (int sl = 0; sl < 2; sl++) {
            const uint32_t sA = s0 + sl*AB_;
            const uint32_t sB = s0 + (2+sl)*AB_;
            #pragma unroll
            for (int ks = 0; ks < 2; ks++) {
                uint32_t bfr[4][2];
                const uint32_t qpb = ((qb + 2*ks) ^ r3b) << 4;
                #pragma unroll
                for (int nt = 0; nt < 4; nt++)
                    ldsm2(bfr[nt], sB + bBase + (uint32_t)(nt * 512) + qpb);
                const uint32_t qpa = ((qa + 2*ks) ^ r3a) << 4;
                #pragma unroll
                for (int mt = 0; mt < 4; mt++) {
                    uint32_t a[4];
                    ldsm4(a, sA + aBase + (uint32_t)(mt * 1024) + qpa);
                    #pragma unroll
                    for (int nt = 0; nt < 4; nt++) mma16816(acc[mt][nt], a, bfr[nt]);
                }
            }
        }
        buf++; if (buf >= 3) buf = 0;
    }

    const int r = lane >> 2, q = lane & 3;
    const float g = (EPI == 1) ? *gp : 0.f;
    #pragma unroll
    for (int mt = 0; mt < 4; mt++) {
        #pragma unroll
        for (int nt = 0; nt < 4; nt++) {
            const int col = bn * 128 + wn * 32 + nt * 8 + q * 2;
            const float2 bb = *(const float2*)(bias + col);
            #pragma unroll
            for (int hh = 0; hh < 2; hh++) {
                const int row = bm * 128 + wm * 64 + mt * 16 + r + hh * 8;
                gemm_epilogue_elem<EPI>(acc[mt][nt][hh*2], acc[mt][nt][hh*2+1], bb,
                    (size_t)row * N + col, Cf, Ch, aux1, aux2, g);
            }
        }
    }
}

// ---------------- GEMM 64x64 tile, fp16, K-chunk 64 (grid-residency fix) -----
// 4 warps, warp wm owns rows wm*16..+15, all 64 cols. 16KB/stage x3 = 48KB.
#define A44_      4096
#define GST44     (4*A44_)              // 16384
#define G44_SMEM  (3*GST44)             // 49152

template<int EPI>
__global__ void __launch_bounds__(128, 4) gemm44_kernel(
    const __half* __restrict__ A, const __half* __restrict__ B,
    const float* __restrict__ bias,
    float* __restrict__ Cf, __half* __restrict__ Ch,
    int M, int N, int K,
    const float* __restrict__ aux1, const float* __restrict__ aux2,
    const float* __restrict__ gp)
{
    extern __shared__ char smp[];
    const uint32_t sb = smem_to_u32(smp);
    const int tid = threadIdx.x;
    const int wm = tid >> 5, lane = tid & 31;
    const int bm = blockIdx.y, bn = blockIdx.x;
    const int NC = K >> 6;

    const size_t Abase = (size_t)bm * 64 * K;
    const size_t Bbase = (size_t)bn * 64 * K;

    float acc[8][4];
    #pragma unroll
    for (int i = 0; i < 8; i++)
        #pragma unroll
        for (int x = 0; x < 4; x++) acc[i][x] = 0.f;

    const int crow = tid >> 2;          // 0..31
    const int cq   = tid & 3;
    const uint32_t so = (uint32_t)(crow * 64 + ((cq ^ (crow & 3)) << 4));

    auto issue = [&](int buf, int kt) {
        const int k0 = kt << 6;
        const uint32_t sbase = sb + buf * GST44;
        const size_t gc = (size_t)crow * K + k0 + cq * 8;
        const size_t gc32 = gc + (size_t)32 * K;
        #pragma unroll
        for (int sl = 0; sl < 2; sl++) {
            cp16(sbase + sl*A44_ + so,              A + Abase + gc + sl*32);
            cp16(sbase + sl*A44_ + so + 2048,       A + Abase + gc32 + sl*32);
            cp16(sbase + (2+sl)*A44_ + so,          B + Bbase + gc + sl*32);
            cp16(sbase + (2+sl)*A44_ + so + 2048,   B + Bbase + gc32 + sl*32);
        }
    };

    issue(0, 0); CP_COMMIT();
    issue(1, 1); CP_COMMIT();

    const uint32_t rowA = (uint32_t)(wm * 16 + (lane & 15));
    const uint32_t qa   = (uint32_t)(lane >> 4);
    const uint32_t r3a  = rowA & 3;
    const uint32_t aBase = rowA * 64;
    const uint32_t rowB = (uint32_t)(lane & 7);
    const uint32_t qb   = (uint32_t)((lane >> 3) & 1);
    const uint32_t r3b  = rowB & 3;
    const uint32_t bBase = rowB * 64;

    int buf = 0;
    for (int c = 0; c < NC; c++) {
        CP_WAIT1();
        __syncthreads();
        if (c + 2 < NC) { int nb = buf + 2; if (nb >= 3) nb -= 3; issue(nb, c + 2); }
        CP_COMMIT();

        const uint32_t s0 = sb + buf * GST44;
        #pragma unroll
        for (int sl = 0; sl < 2; sl++) {
            const uint32_t sA = s0 + sl*A44_;
            const uint32_t sB = s0 + (2+sl)*A44_;
            #pragma unroll
            for (int ks = 0; ks < 2; ks++) {
                uint32_t bfr[8][2];
                const uint32_t qpb = ((qb + 2*ks) ^ r3b) << 4;
                #pragma unroll
                for (int nt = 0; nt < 8; nt++)
                    ldsm2(bfr[nt], sB + bBase + (uint32_t)(nt * 512) + qpb);
                const uint32_t qpa = ((qa + 2*ks) ^ r3a) << 4;
                uint32_t a[4];
                ldsm4(a, sA + aBase + qpa);
                #pragma unroll
                for (int nt = 0; nt < 8; nt++) mma16816(acc[nt], a, bfr[nt]);
            }
        }
        buf++; if (buf >= 3) buf = 0;
    }

    const int r = lane >> 2, q = lane & 3;
    const float g = (EPI == 1) ? *gp : 0.f;
    #pragma unroll
    for (int nt = 0; nt < 8; nt++) {
        const int col = bn * 64 + nt * 8 + q * 2;
        const float2 bb = *(const float2*)(bias + col);
        #pragma unroll
        for (int hh = 0; hh < 2; hh++) {
            const int row = bm * 64 + wm * 16 + r + hh * 8;
            gemm_epilogue_elem<EPI>(acc[nt][hh*2], acc[nt][hh*2+1], bb,
                (size_t)row * N + col, Cf, Ch, aux1, aux2, g);
        }
    }
}

// ---------------- fused attention (128 threads): flash (512) + memattn ------
#define FROW 144
#define FLASH_SMEM (3*9216)

__device__ void memattn_body(const __half* __restrict__ qkv,
                             const float* __restrict__ mkv,
                             float* __restrict__ outm, int row)
{
    const int tid = threadIdx.x;
    const int h = tid >> 3, t8 = tid & 7;
    __shared__ float sc[NH * MM];
    const int co = h * 64 + t8 * 8;
    uint4 qraw = *(const uint4*)(qkv + (size_t)row * 3072 + co);
    float qv[8];
    {
        __half2* qh = (__half2*)&qraw;
        #pragma unroll
        for (int i = 0; i < 4; i++) {
            qv[2*i]   = __low2float(qh[i])  * 0.125f;
            qv[2*i+1] = __high2float(qh[i]) * 0.125f;
        }
    }
    const float* kbase = mkv + (size_t)row * MM * 2 * DMODEL;
    #pragma unroll 4
    for (int m = 0; m < MM; m++) {
        const float* kp = kbase + (size_t)m * 2 * DMODEL + co;
        float4 k0 = *(const float4*)(kp);
        float4 k1 = *(const float4*)(kp + 4);
        float d = qv[0]*k0.x + qv[1]*k0.y + qv[2]*k0.z + qv[3]*k0.w
                + qv[4]*k1.x + qv[5]*k1.y + qv[6]*k1.z + qv[7]*k1.w;
        #pragma unroll
        for (int o = 4; o; o >>= 1) d += __shfl_xor_sync(0xffffffffu, d, o);
        if (t8 == 0) sc[h * MM + m] = d;
    }
    __syncthreads();
    if (tid < NH) {
        float mx = -1e30f;
        #pragma unroll
        for (int m = 0; m < MM; m++) mx = fmaxf(mx, sc[tid * MM + m]);
        float s = 0.f;
        #pragma unroll
        for (int m = 0; m < MM; m++) {
            float e = __expf(sc[tid * MM + m] - mx);
            sc[tid * MM + m] = e; s += e;
        }
        float inv = 1.f / s;
        #pragma unroll
        for (int m = 0; m < MM; m++) sc[tid * MM + m] *= inv;
    }
    __syncthreads();
    float a0 = 0.f, a1 = 0.f, a2 = 0.f, a3 = 0.f, a4 = 0.f, a5 = 0.f, a6 = 0.f, a7 = 0.f;
    #pragma unroll 4
    for (int m = 0; m < MM; m++) {
        float w = sc[h * MM + m];
        const float* vp = kbase + (size_t)m * 2 * DMODEL + DMODEL + co;
        float4 v0 = *(const float4*)(vp);
        float4 v1 = *(const float4*)(vp + 4);
        a0 += w*v0.x; a1 += w*v0.y; a2 += w*v0.z; a3 += w*v0.w;
        a4 += w*v1.x; a5 += w*v1.y; a6 += w*v1.z; a7 += w*v1.w;
    }
    float* op = outm + (size_t)row * DMODEL + co;
    *(float4*)(op)     = make_float4(a0, a1, a2, a3);
    *(float4*)(op + 4) = make_float4(a4, a5, a6, a7);
}

__device__ void flash_body(const __half* __restrict__ qkv,
                           __half* __restrict__ outO,
                           char* sm, int fb)
{
    const int tid = threadIdx.x, lane = tid & 31, wm = tid >> 5;
    const int qt = 15 - (fb & 15);
    const int bhh = fb >> 4, b = bhh >> 4, h = bhh & 15;
    const int qbase = qt * 64;
    const size_t srow = (size_t)b * SEQ;

    char* Qs = sm;
    char* Ks = sm + 9216;
    char* Vs = sm + 2*9216;

    const int lrow = tid >> 1;
    const int lh   = (tid & 1) * 32;

    {
        const __half* gq = qkv + (srow + qbase + lrow) * 3072 + h * 64 + lh;
        char* qd = Qs + lrow * FROW + lh * 2;
        *(uint4*)(qd)      = *(const uint4*)(gq);
        *(uint4*)(qd + 16) = *(const uint4*)(gq + 8);
        *(uint4*)(qd + 32) = *(const uint4*)(gq + 16);
        *(uint4*)(qd + 48) = *(const uint4*)(gq + 24);
    }

    const int r = lane >> 2, q = lane & 3;
    float m0 = -1e30f, m1 = -1e30f, l0 = 0.f, l1 = 0.f;
    float o[8][4];
    #pragma unroll
    for (int i = 0; i < 8; i++) o[i][0]=o[i][1]=o[i][2]=o[i][3]=0.f;

    const uint32_t QA = smem_to_u32(Qs);
    const uint32_t qaddr0 = QA + (uint32_t)((wm*16 + (lane & 15)) * FROW + ((lane >> 4) & 1) * 16);
    const uint32_t kaddr0 = QA + 9216 + (uint32_t)((lane & 7) * FROW + ((lane >> 3) & 1) * 16);
    const uint32_t vaddr0 = QA + 2*9216 + (uint32_t)((lane & 15) * FROW);

    for (int kt = 0; kt <= qt; kt++) {
        __syncthreads();
        {
            const __half* gk = qkv + (srow + kt*64 + lrow) * 3072 + 1024 + h * 64 + lh;
            char* kd = Ks + lrow * FROW + lh * 2;
            *(uint4*)(kd)      = *(const uint4*)(gk);
            *(uint4*)(kd + 16) = *(const uint4*)(gk + 8);
            *(uint4*)(kd + 32) = *(const uint4*)(gk + 16);
            *(uint4*)(kd + 48) = *(const uint4*)(gk + 24);
            char* vd = Vs + lrow * FROW + lh * 2;
            *(uint4*)(vd)      = *(const uint4*)(gk + 1024);
            *(uint4*)(vd + 16) = *(const uint4*)(gk + 1024 + 8);
            *(uint4*)(vd + 32) = *(const uint4*)(gk + 1024 + 16);
            *(uint4*)(vd + 48) = *(const uint4*)(gk + 1024 + 24);
        }
        __syncthreads();

        float s[8][4];
        #pragma unroll
        for (int nt = 0; nt < 8; nt++) s[nt][0]=s[nt][1]=s[nt][2]=s[nt][3]=0.f;
        #pragma unroll
        for (int ks = 0; ks < 4; ks++) {
            uint32_t aQ[4];
            ldsm4(aQ, qaddr0 + ks*32);
            uint32_t bK[8][2];
            #pragma unroll
            for (int nt = 0; nt < 8; nt++)
                ldsm2(bK[nt], kaddr0 + (uint32_t)(nt * 8 * FROW + ks * 32));
            #pragma unroll
            for (int nt = 0; nt < 8; nt++) mma16816(s[nt], aQ, bK[nt]);
        }
        #pragma unroll
        for (int nt = 0; nt < 8; nt++) {
            s[nt][0] *= 0.125f; s[nt][1] *= 0.125f;
            s[nt][2] *= 0.125f; s[nt][3] *= 0.125f;
        }

        if (kt == qt) {
            const int r0 = wm*16 + r;
            #pragma unroll
            for (int nt = 0; nt < 8; nt++) {
                const int cb = nt*8 + q*2;
                if (cb     > r0)     s[nt][0] = -1e30f;
                if (cb + 1 > r0)     s[nt][1] = -1e30f;
                if (cb     > r0 + 8) s[nt][2] = -1e30f;
                if (cb + 1 > r0 + 8) s[nt][3] = -1e30f;
            }
        }

        float mx0 = -1e30f, mx1 = -1e30f;
        #pragma unroll
        for (int nt = 0; nt < 8; nt++) {
            mx0 = fmaxf(mx0, fmaxf(s[nt][0], s[nt][1]));
            mx1 = fmaxf(mx1, fmaxf(s[nt][2], s[nt][3]));
        }
        mx0 = fmaxf(mx0, __shfl_xor_sync(0xffffffffu, mx0, 1));
        mx0 = fmaxf(mx0, __shfl_xor_sync(0xffffffffu, mx0, 2));
        mx1 = fmaxf(mx1, __shfl_xor_sync(0xffffffffu, mx1, 1));
        mx1 = fmaxf(mx1, __shfl_xor_sync(0xffffffffu, mx1, 2));
        const float mn0 = fmaxf(m0, mx0);
        const float mn1 = fmaxf(m1, mx1);
        const float al0 = __expf(m0 - mn0), al1 = __expf(m1 - mn1);
        float sum0 = 0.f, sum1 = 0.f;
        #pragma unroll
        for (int nt = 0; nt < 8; nt++) {
            s[nt][0] = __expf(s[nt][0] - mn0);
            s[nt][1] = __expf(s[nt][1] - mn0);
            s[nt][2] = __expf(s[nt][2] - mn1);
            s[nt][3] = __expf(s[nt][3] - mn1);
            sum0 += s[nt][0] + s[nt][1];
            sum1 += s[nt][2] + s[nt][3];
        }
        sum0 += __shfl_xor_sync(0xffffffffu, sum0, 1);
        sum0 += __shfl_xor_sync(0xffffffffu, sum0, 2);
        sum1 += __shfl_xor_sync(0xffffffffu, sum1, 1);
        sum1 += __shfl_xor_sync(0xffffffffu, sum1, 2);
        l0 = al0 * l0 + sum0;
        l1 = al1 * l1 + sum1;
        m0 = mn0; m1 = mn1;
        #pragma unroll
        for (int i = 0; i < 8; i++) {
            o[i][0] *= al0; o[i][1] *= al0; o[i][2] *= al1; o[i][3] *= al1;
        }

        uint32_t aP[4][4];
        #pragma unroll
        for (int ks = 0; ks < 4; ks++) {
            const int n0 = 2*ks, n1 = 2*ks + 1;
            aP[ks][0] = pack_h2(s[n0][0], s[n0][1]);
            aP[ks][1] = pack_h2(s[n0][2], s[n0][3]);
            aP[ks][2] = pack_h2(s[n1][0], s[n1][1]);
            aP[ks][3] = pack_h2(s[n1][2], s[n1][3]);
        }
        #pragma unroll
        for (int ks = 0; ks < 4; ks++) {
            #pragma unroll
            for (int gq4 = 0; gq4 < 2; gq4++) {
                uint32_t bV[4][2];
                #pragma unroll
                for (int j = 0; j < 4; j++)
                    ldsm2t(bV[j], vaddr0 + (uint32_t)(ks * 16 * FROW + (gq4*4 + j) * 16));
                #pragma unroll
                for (int j = 0; j < 4; j++) mma16816(o[gq4*4+j], aP[ks], bV[j]);
            }
        }
    }

    const float i0 = 1.f / l0, i1 = 1.f / l1;
    #pragma unroll
    for (int ntv = 0; ntv < 8; ntv++) {
        const int rg = wm*16 + r, cg = ntv*8 + q*2;
        const size_t o0 = (srow + qbase + rg) * (size_t)DMODEL + h*64 + cg;
        const size_t o1 = o0 + 8 * DMODEL;
        *(uint32_t*)(outO + o0) = pack_h2(o[ntv][0] * i0, o[ntv][1] * i0);
        *(uint32_t*)(outO + o1) = pack_h2(o[ntv][2] * i1, o[ntv][3] * i1);
    }
}

__global__ void __launch_bounds__(128) attn_kernel(
    const __half* __restrict__ qkv, const float* __restrict__ mkv,
    float* __restrict__ outm, __half* __restrict__ outO)
{
    extern __shared__ char sm[];
    if (blockIdx.x < 512) {
        flash_body(qkv, outO, sm, blockIdx.x);
    } else {
        memattn_body(qkv, mkv, outm, blockIdx.x - 512);
    }
}

// ------------------------------ launcher ------------------------------------
extern "C" void kernel_launch(void* const* d_in, const int* in_sizes, int n_in,
                              void* d_out, int out_size)
{
    (void)in_sizes; (void)n_in; (void)out_size;
    const float* prev  = (const float*)d_in[0];
    const float* memkv = (const float*)d_in[1];
    const float* gval  = (const float*)d_in[2];
    const float* ln1g  = (const float*)d_in[3];
    const float* ln1b  = (const float*)d_in[4];
    const float* attnw = (const float*)d_in[5];
    const float* attnb = (const float*)d_in[6];
    const float* cprw  = (const float*)d_in[7];
    const float* cprb  = (const float*)d_in[8];
    const float* ln2g  = (const float*)d_in[9];
    const float* ln2b  = (const float*)d_in[10];
    const float* fcw   = (const float*)d_in[11];
    const float* fcb   = (const float*)d_in[12];
    const float* pw    = (const float*)d_in[13];
    const float* pb    = (const float*)d_in[14];
    float* out = (float*)d_out;

    float *mem, *hid;
    __half *qkv, *h1, *att, *h2, *ff, *wq, *wp, *wf, *wo;
    cudaGetSymbolAddress((void**)&qkv, g_qkv);
    cudaGetSymbolAddress((void**)&mem, g_mem);
    cudaGetSymbolAddress((void**)&hid, g_hid);
    cudaGetSymbolAddress((void**)&h1,  g_h1);
    cudaGetSymbolAddress((void**)&att, g_att);
    cudaGetSymbolAddress((void**)&h2,  g_h2);
    cudaGetSymbolAddress((void**)&ff,  g_ff);
    cudaGetSymbolAddress((void**)&wq,  g_wq);
    cudaGetSymbolAddress((void**)&wp,  g_wp);
    cudaGetSymbolAddress((void**)&wf,  g_wf);
    cudaGetSymbolAddress((void**)&wo,  g_wo);

    cudaFuncSetAttribute(attn_kernel, cudaFuncAttributeMaxDynamicSharedMemorySize, FLASH_SMEM);
    cudaFuncSetAttribute(gemm_mma_kernel<4>, cudaFuncAttributeMaxDynamicSharedMemorySize, GEMM_SMEM);
    cudaFuncSetAttribute(gemm_mma_kernel<2>, cudaFuncAttributeMaxDynamicSharedMemorySize, GEMM_SMEM);
    cudaFuncSetAttribute(gemm44_kernel<1>, cudaFuncAttributeMaxDynamicSharedMemorySize, G44_SMEM);
    cudaFuncSetAttribute(gemm44_kernel<3>, cudaFuncAttributeMaxDynamicSharedMemorySize, G44_SMEM);

    // 1) prep: LN1 + all weight converts (fused, consolidated)
    prep_kernel<<<2048 + 768 + 256 + 1024 + 1024, 256>>>(prev, ln1g, ln1b, h1,
        attnw, wq, cprw, wp, fcw, wf, pw, wo);
    // 2) qkv = h1 @ c_attn + b (fp16)
    gemm_mma_kernel<4><<<dim3(24, 16), 256, GEMM_SMEM>>>(h1, wq, attnb,
        nullptr, qkv, ROWS, 3*DMODEL, DMODEL, nullptr, nullptr, nullptr);
    // 3) fused flash-mma + memattn (128 threads)
    attn_kernel<<<512 + 2048, 128, FLASH_SMEM>>>(qkv, memkv, mem, att);
    // 4) hid = (1-g)*(att@c_proj+b) + g*mem + prev   (64x64, grid 512, 1 wave)
    gemm44_kernel<1><<<dim3(16, 32), 128, G44_SMEM>>>(att, wp, cprb,
        hid, nullptr, ROWS, DMODEL, DMODEL, mem, prev, gval);
    // 5) LN2 -> h2
    prep_kernel<<<2048, 256>>>(hid, ln2g, ln2b, h2,
        nullptr, nullptr, nullptr, nullptr, nullptr, nullptr, nullptr, nullptr);
    // 6) ff = gelu(h2 @ fc + b) -> fp16
    gemm_mma_kernel<2><<<dim3(32, 16), 256, GEMM_SMEM>>>(h2, wf, fcb,
        nullptr, ff, ROWS, 4*DMODEL, DMODEL, nullptr, nullptr, nullptr);
    // 7) out = ff @ proj + b + hid   (64x64, grid 512, 1 wave)
    gemm44_kernel<3><<<dim3(16, 32), 128, G44_SMEM>>>(ff, wo, pb,
        out, nullptr, ROWS, DMODEL, 4*DMODEL, hid, nullptr, nullptr);
}

// round 15
// speedup vs baseline: 1.1023x; 1.1023x over previous
#include <cuda_runtime.h>
#include <cuda_fp16.h>
#include <cstdint>

#define BS_    2
#define SEQ    1024
#define DMODEL 1024
#define NH     16
#define HD     64
#define MM     32
#define ROWS   (BS_*SEQ)

// ---------------- scratch (device globals) ----------------
__device__ __half g_qkv[ROWS*3*DMODEL];
__device__ float g_mem[ROWS*DMODEL];
__device__ float g_hid[ROWS*DMODEL];
__device__ __half g_h1 [ROWS*DMODEL];
__device__ __half g_att[ROWS*DMODEL];
__device__ __half g_h2 [ROWS*DMODEL];
__device__ __half g_ff [ROWS*4*DMODEL];
__device__ __half g_wq[DMODEL*3*DMODEL];
__device__ __half g_wp[DMODEL*DMODEL];
__device__ __half g_wf[DMODEL*4*DMODEL];
__device__ __half g_wo[4*DMODEL*DMODEL];

// ---------------- helpers ----------------
__device__ __forceinline__ uint32_t smem_to_u32(const void* p) {
    uint32_t a;
    asm("{ .reg .u64 t; cvta.to.shared.u64 t, %1; cvt.u32.u64 %0, t; }" : "=r"(a) : "l"(p));
    return a;
}
__device__ __forceinline__ void cp16(uint32_t s, const void* g) {
    asm volatile("cp.async.cg.shared.global [%0], [%1], 16;" :: "r"(s), "l"(g));
}
#define CP_COMMIT() asm volatile("cp.async.commit_group;" ::: "memory")
#define CP_WAIT1()  asm volatile("cp.async.wait_group 1;" ::: "memory")
#define CP_WAIT0()  asm volatile("cp.async.wait_group 0;" ::: "memory")

__device__ __forceinline__ void ldsm4(uint32_t* r, uint32_t addr) {
    asm volatile("ldmatrix.sync.aligned.m8n8.x4.shared.b16 {%0,%1,%2,%3}, [%4];"
        : "=r"(r[0]), "=r"(r[1]), "=r"(r[2]), "=r"(r[3]) : "r"(addr));
}
__device__ __forceinline__ void ldsm2(uint32_t* r, uint32_t addr) {
    asm volatile("ldmatrix.sync.aligned.m8n8.x2.shared.b16 {%0,%1}, [%2];"
        : "=r"(r[0]), "=r"(r[1]) : "r"(addr));
}
__device__ __forceinline__ void ldsm2t(uint32_t* r, uint32_t addr) {
    asm volatile("ldmatrix.sync.aligned.m8n8.x2.trans.shared.b16 {%0,%1}, [%2];"
        : "=r"(r[0]), "=r"(r[1]) : "r"(addr));
}
__device__ __forceinline__ void mma16816(float* d, const uint32_t* a, const uint32_t* b) {
    asm volatile(
      "mma.sync.aligned.m16n8k16.row.col.f32.f16.f16.f32 "
      "{%0,%1,%2,%3}, {%4,%5,%6,%7}, {%8,%9}, {%0,%1,%2,%3};"
      : "+f"(d[0]), "+f"(d[1]), "+f"(d[2]), "+f"(d[3])
      : "r"(a[0]), "r"(a[1]), "r"(a[2]), "r"(a[3]), "r"(b[0]), "r"(b[1]));
}

__device__ __forceinline__ float gelu_new(float x) {
    float x3 = x * x * x;
    float t  = tanhf(0.7978845608028654f * (x + 0.044715f * x3));
    return 0.5f * x * (1.f + t);
}
__device__ __forceinline__ uint32_t pack_h2(float x, float y) {
    __half2 t = __floats2half2_rn(x, y);
    return *reinterpret_cast<uint32_t*>(&t);
}

// ---------------- prep: fused 4x weight-convert + LN -----------------------
__device__ void wconv_body(float* shm,
    const float* __restrict__ W, __half* __restrict__ hi,
    int K, int N, int bx, int by)
{
    float (*s)[33] = (float(*)[33])shm;
    const int tx = threadIdx.x & 31, ty = threadIdx.x >> 5;
    const int n0 = bx * 32, k0 = by * 32;
    #pragma unroll
    for (int i = 0; i < 4; i++)
        s[ty + 8*i][tx] = W[(size_t)(k0 + ty + 8*i) * N + n0 + tx];
    __syncthreads();
    #pragma unroll
    for (int i = 0; i < 4; i++) {
        int n = ty + 8*i;
        hi[(size_t)(n0 + n) * K + k0 + tx] = __float2half(s[tx][n]);
    }
    __syncthreads();
}

__device__ void wconv4_body(float* shm,
    const float* __restrict__ W, __half* __restrict__ hi,
    int K, int N, int bxg, int by)
{
    #pragma unroll
    for (int t = 0; t < 4; t++)
        wconv_body(shm, W, hi, K, N, bxg * 4 + t, by);
}

__device__ void ln_body(float* shm, int row,
    const float* __restrict__ x, const float* __restrict__ g,
    const float* __restrict__ b, __half* __restrict__ y)
{
    const int tid = threadIdx.x;
    float* rs = shm; float* rs2 = shm + 8;
    const float* xr = x + (size_t)row * DMODEL;
    float4 v = *(const float4*)(xr + tid * 4);
    float s  = v.x + v.y + v.z + v.w;
    float s2 = v.x*v.x + v.y*v.y + v.z*v.z + v.w*v.w;
    #pragma unroll
    for (int o = 16; o; o >>= 1) {
        s  += __shfl_xor_sync(0xffffffffu, s,  o);
        s2 += __shfl_xor_sync(0xffffffffu, s2, o);
    }
    const int w = tid >> 5, l = tid & 31;
    if (!l) { rs[w] = s; rs2[w] = s2; }
    __syncthreads();
    s = 0.f; s2 = 0.f;
    #pragma unroll
    for (int i = 0; i < 8; i++) { s += rs[i]; s2 += rs2[i]; }
    const float mean = s * (1.f / DMODEL);
    const float var  = s2 * (1.f / DMODEL) - mean * mean;
    const float rstd = rsqrtf(var + 1e-5f);
    const int c = tid * 4;
    float4 gg = *(const float4*)(g + c);
    float4 bb = *(const float4*)(b + c);
    float4 o;
    o.x = (v.x - mean) * rstd * gg.x + bb.x;
    o.y = (v.y - mean) * rstd * gg.y + bb.y;
    o.z = (v.z - mean) * rstd * gg.z + bb.z;
    o.w = (v.w - mean) * rstd * gg.w + bb.w;
    uint2 hh;
    hh.x = pack_h2(o.x, o.y); hh.y = pack_h2(o.z, o.w);
    *(uint2*)(y + (size_t)row * DMODEL + c) = hh;
}

__global__ void __launch_bounds__(256) prep_kernel(
    const float* prev, const float* ln1g, const float* ln1b, __half* h1,
    const float* attnw, __half* wq,
    const float* cprw,  __half* wp,
    const float* fcw,   __half* wf,
    const float* pw,    __half* wo)
{
    __shared__ float shm[32*33];
    int idx = blockIdx.x;
    if (idx < 2048) { ln_body(shm, idx, prev, ln1g, ln1b, h1); return; }
    idx -= 2048;
    if (idx < 768)  { wconv4_body(shm, attnw, wq, 1024, 3072, idx % 24, idx / 24); return; }
    idx -= 768;
    if (idx < 256)  { wconv4_body(shm, cprw, wp, 1024, 1024, idx % 8, idx / 8); return; }
    idx -= 256;
    if (idx < 1024) { wconv4_body(shm, fcw, wf, 1024, 4096, idx % 32, idx / 32); return; }
    idx -= 1024;
    wconv4_body(shm, pw, wo, 4096, 1024, idx % 8, idx / 8);
}

// ---------------- epilogue (shared) -----------------------------------------
template<int EPI>
__device__ __forceinline__ void gemm_epilogue_elem(
    float v0, float v1, const float2 bb, size_t o,
    float* Cf, __half* Ch,
    const float* aux1, const float* aux2, float g)
{
    v0 += bb.x; v1 += bb.y;
    if (EPI == 1) {
        float2 a1 = *(const float2*)(aux1 + o);
        float2 a2 = *(const float2*)(aux2 + o);
        v0 = (1.f - g) * v0 + g * a1.x + a2.x;
        v1 = (1.f - g) * v1 + g * a1.y + a2.y;
    }
    if (EPI == 3) {
        float2 a1 = *(const float2*)(aux1 + o);
        v0 += a1.x; v1 += a1.y;
    }
    if (EPI == 2) {
        v0 = gelu_new(v0); v1 = gelu_new(v1);
        *(uint32_t*)(Ch + o) = pack_h2(v0, v1);
    } else if (EPI == 4) {
        *(uint32_t*)(Ch + o) = pack_h2(v0, v1);
    } else {
        *(float2*)(Cf + o) = make_float2(v0, v1);
    }
}

// ---------------- GEMM 128x128 tile, fp16, K-chunk 64 ------------------------
#define AB_     8192
#define GSTAGE  (4*AB_)                 // 32768
#define GEMM_SMEM (3*GSTAGE)            // 98304

template<int EPI>
__global__ void __launch_bounds__(256, 2) gemm_mma_kernel(
    const __half* __restrict__ A, const __half* __restrict__ B,
    const float* __restrict__ bias,
    float* __restrict__ Cf, __half* __restrict__ Ch,
    int M, int N, int K,
    const float* __restrict__ aux1, const float* __restrict__ aux2,
    const float* __restrict__ gp)
{
    extern __shared__ char smp[];
    const uint32_t sb = smem_to_u32(smp);
    const int tid = threadIdx.x;
    const int wid = tid >> 5, lane = tid & 31;
    const int wm = wid & 1, wn = wid >> 1;
    const int bm = blockIdx.y, bn = blockIdx.x;
    const int NC = K >> 6;

    const size_t Abase = (size_t)bm * 128 * K;
    const size_t Bbase = (size_t)bn * 128 * K;

    float acc[4][4][4];
    #pragma unroll
    for (int i = 0; i < 4; i++)
        #pragma unroll
        for (int j = 0; j < 4; j++)
            #pragma unroll
            for (int x = 0; x < 4; x++) acc[i][j][x] = 0.f;

    const int crow = tid >> 2;
    const int cq   = tid & 3;
    const uint32_t so0 = (uint32_t)(crow * 64 + ((cq ^ (crow & 3)) << 4));
    const uint32_t so1 = so0 + 64 * 64;

    auto issue = [&](int buf, int kt) {
        const int k0 = kt << 6;
        const uint32_t sbase = sb + buf * GSTAGE;
        const size_t g0 = (size_t)crow * K + k0 + cq * 8;
        const size_t g1 = g0 + (size_t)64 * K;
        #pragma unroll
        for (int sl = 0; sl < 2; sl++) {
            cp16(sbase + sl*AB_ + so0,          A + Abase + g0 + sl*32);
            cp16(sbase + sl*AB_ + so1,          A + Abase + g1 + sl*32);
            cp16(sbase + (2+sl)*AB_ + so0,      B + Bbase + g0 + sl*32);
            cp16(sbase + (2+sl)*AB_ + so1,      B + Bbase + g1 + sl*32);
        }
    };

    issue(0, 0); CP_COMMIT();
    issue(1, 1); CP_COMMIT();

    const uint32_t rowA = (uint32_t)(wm * 64 + (lane & 15));
    const uint32_t qa   = (uint32_t)(lane >> 4);
    const uint32_t r3a  = rowA & 3;
    const uint32_t aBase = rowA * 64;
    const uint32_t rowB = (uint32_t)(wn * 32 + (lane & 7));
    const uint32_t qb   = (uint32_t)((lane >> 3) & 1);
    const uint32_t r3b  = rowB & 3;
    const uint32_t bBase = rowB * 64;

    int buf = 0;
    for (int c = 0; c < NC; c++) {
        CP_WAIT1();
        __syncthreads();
        if (c + 2 < NC) { int nb = buf + 2; if (nb >= 3) nb -= 3; issue(nb, c + 2); }
        CP_COMMIT();

        const uint32_t s0 = sb + buf * GSTAGE;
        #pragma unroll
        for (int sl = 0; sl < 2; sl++) {
            const uint32_t sA = s0 + sl*AB_;
            const uint32_t sB = s0 + (2+sl)*AB_;
            #pragma unroll
            for (int ks = 0; ks < 2; ks++) {
                uint32_t bfr[4][2];
                const uint32_t qpb = ((qb + 2*ks) ^ r3b) << 4;
                #pragma unroll
                for (int nt = 0; nt < 4; nt++)
                    ldsm2(bfr[nt], sB + bBase + (uint32_t)(nt * 512) + qpb);
                const uint32_t qpa = ((qa + 2*ks) ^ r3a) << 4;
                #pragma unroll
                for (int mt = 0; mt < 4; mt++) {
                    uint32_t a[4];
                    ldsm4(a, sA + aBase + (uint32_t)(mt * 1024) + qpa);
                    #pragma unroll
                    for (int nt = 0; nt < 4; nt++) mma16816(acc[mt][nt], a, bfr[nt]);
                }
            }
        }
        buf++; if (buf >= 3) buf = 0;
    }

    const int r = lane >> 2, q = lane & 3;
    const float g = (EPI == 1) ? *gp : 0.f;
    #pragma unroll
    for (int mt = 0; mt < 4; mt++) {
        #pragma unroll
        for (int nt = 0; nt < 4; nt++) {
            const int col = bn * 128 + wn * 32 + nt * 8 + q * 2;
            const float2 bb = *(const float2*)(bias + col);
            #pragma unroll
            for (int hh = 0; hh < 2; hh++) {
                const int row = bm * 128 + wm * 64 + mt * 16 + r + hh * 8;
                gemm_epilogue_elem<EPI>(acc[mt][nt][hh*2], acc[mt][nt][hh*2+1], bb,
                    (size_t)row * N + col, Cf, Ch, aux1, aux2, g);
            }
        }
    }
}

// ---------------- GEMM 64x128 tile, fp16, K-chunk 64 (R13 proven) ------------
#define A64_      4096
#define B64_      8192
#define GSTAGE64  (2*A64_ + 2*B64_)     // 24576
#define GEMM64_SMEM (3*GSTAGE64)        // 73728

template<int EPI>
__global__ void __launch_bounds__(128, 3) gemm_mma64_kernel(
    const __half* __restrict__ A, const __half* __restrict__ B,
    const float* __restrict__ bias,
    float* __restrict__ Cf, __half* __restrict__ Ch,
    int M, int N, int K,
    const float* __restrict__ aux1, const float* __restrict__ aux2,
    const float* __restrict__ gp)
{
    extern __shared__ char smp[];
    const uint32_t sb = smem_to_u32(smp);
    const int tid = threadIdx.x;
    const int wn = tid >> 5, lane = tid & 31;
    const int bm = blockIdx.y, bn = blockIdx.x;
    const int NC = K >> 6;

    const size_t Abase = (size_t)bm * 64 * K;
    const size_t Bbase = (size_t)bn * 128 * K;

    float acc[4][4][4];
    #pragma unroll
    for (int i = 0; i < 4; i++)
        #pragma unroll
        for (int j = 0; j < 4; j++)
            #pragma unroll
            for (int x = 0; x < 4; x++) acc[i][j][x] = 0.f;

    const int crow = tid >> 2;
    const int cq   = tid & 3;
    const uint32_t soA = (uint32_t)(crow * 64 + ((cq ^ (crow & 3)) << 4));

    auto issue = [&](int buf, int kt) {
        const int k0 = kt << 6;
        const uint32_t sbase = sb + buf * GSTAGE64;
        const size_t gc = (size_t)crow * K + k0 + cq * 8;
        #pragma unroll
        for (int sl = 0; sl < 2; sl++) {
            cp16(sbase + sl*A64_ + soA,        A + Abase + gc + sl*32);
            cp16(sbase + sl*A64_ + soA + 2048, A + Abase + gc + sl*32 + (size_t)32 * K);
            #pragma unroll
            for (int j = 0; j < 4; j++)
                cp16(sbase + 2*A64_ + sl*B64_ + soA + j*2048,
                     B + Bbase + gc + sl*32 + (size_t)(32 * j) * K);
        }
    };

    issue(0, 0); CP_COMMIT();
    issue(1, 1); CP_COMMIT();

    const uint32_t rowA = (uint32_t)(lane & 15);
    const uint32_t qa   = (uint32_t)(lane >> 4);
    const uint32_t r3a  = rowA & 3;
    const uint32_t aBase = rowA * 64;
    const uint32_t rowB = (uint32_t)(wn * 32 + (lane & 7));
    const uint32_t qb   = (uint32_t)((lane >> 3) & 1);
    const uint32_t r3b  = rowB & 3;
    const uint32_t bBase = rowB * 64;

    int buf = 0;
    for (int c = 0; c < NC; c++) {
        CP_WAIT1();
        __syncthreads();
        if (c + 2 < NC) { int nb = buf + 2; if (nb >= 3) nb -= 3; issue(nb, c + 2); }
        CP_COMMIT();

        const uint32_t s0 = sb + buf * GSTAGE64;
        #pragma unroll
        for (int sl = 0; sl < 2; sl++) {
            const uint32_t sA = s0 + sl*A64_;
            const uint32_t sB = s0 + 2*A64_ + sl*B64_;
            #pragma unroll
            for (int ks = 0; ks < 2; ks++) {
                uint32_t bfr[4][2];
                const uint32_t qpb = ((qb + 2*ks) ^ r3b) << 4;
                #pragma unroll
                for (int nt = 0; nt < 4; nt++)
                    ldsm2(bfr[nt], sB + bBase + (uint32_t)(nt * 512) + qpb);
                const uint32_t qpa = ((qa + 2*ks) ^ r3a) << 4;
                #pragma unroll
                for (int mt = 0; mt < 4; mt++) {
                    uint32_t a[4];
                    ldsm4(a, sA + aBase + (uint32_t)(mt * 1024) + qpa);
                    #pragma unroll
                    for (int nt = 0; nt < 4; nt++) mma16816(acc[mt][nt], a, bfr[nt]);
                }
            }
        }
        buf++; if (buf >= 3) buf = 0;
    }

    const int r = lane >> 2, q = lane & 3;
    const float g = (EPI == 1) ? *gp : 0.f;
    #pragma unroll
    for (int mt = 0; mt < 4; mt++) {
        #pragma unroll
        for (int nt = 0; nt < 4; nt++) {
            const int col = bn * 128 + wn * 32 + nt * 8 + q * 2;
            const float2 bb = *(const float2*)(bias + col);
            #pragma unroll
            for (int hh = 0; hh < 2; hh++) {
                const int row = bm * 64 + mt * 16 + r + hh * 8;
                gemm_epilogue_elem<EPI>(acc[nt == nt ? mt : mt][nt][hh*2], acc[mt][nt][hh*2+1], bb,
                    (size_t)row * N + col, Cf, Ch, aux1, aux2, g);
            }
        }
    }
}

// ---------------- fused attention (128 threads): flash (512) + memattn ------
// flash: 4 warps, warp-autonomous rows; cp.async 2-buffer K/V pipeline.
// smem: Q (9216) | {K,V} x2 buffers (18432 each) = 46080.
#define FROW 144
#define KVBUF (2*9216)
#define FLASH_SMEM (9216 + 2*KVBUF)

__device__ void memattn_body(const __half* __restrict__ qkv,
                             const float* __restrict__ mkv,
                             float* __restrict__ outm, int row)
{
    const int tid = threadIdx.x;
    const int h = tid >> 3, t8 = tid & 7;
    __shared__ float sc[NH * MM];
    const int co = h * 64 + t8 * 8;
    uint4 qraw = *(const uint4*)(qkv + (size_t)row * 3072 + co);
    float qv[8];
    {
        __half2* qh = (__half2*)&qraw;
        #pragma unroll
        for (int i = 0; i < 4; i++) {
            qv[2*i]   = __low2float(qh[i])  * 0.125f;
            qv[2*i+1] = __high2float(qh[i]) * 0.125f;
        }
    }
    const float* kbase = mkv + (size_t)row * MM * 2 * DMODEL;
    #pragma unroll 4
    for (int m = 0; m < MM; m++) {
        const float* kp = kbase + (size_t)m * 2 * DMODEL + co;
        float4 k0 = *(const float4*)(kp);
        float4 k1 = *(const float4*)(kp + 4);
        float d = qv[0]*k0.x + qv[1]*k0.y + qv[2]*k0.z + qv[3]*k0.w
                + qv[4]*k1.x + qv[5]*k1.y + qv[6]*k1.z + qv[7]*k1.w;
        #pragma unroll
        for (int o = 4; o; o >>= 1) d += __shfl_xor_sync(0xffffffffu, d, o);
        if (t8 == 0) sc[h * MM + m] = d;
    }
    __syncthreads();
    if (tid < NH) {
        float mx = -1e30f;
        #pragma unroll
        for (int m = 0; m < MM; m++) mx = fmaxf(mx, sc[tid * MM + m]);
        float s = 0.f;
        #pragma unroll
        for (int m = 0; m < MM; m++) {
            float e = __expf(sc[tid * MM + m] - mx);
            sc[tid * MM + m] = e; s += e;
        }
        float inv = 1.f / s;
        #pragma unroll
        for (int m = 0; m < MM; m++) sc[tid * MM + m] *= inv;
    }
    __syncthreads();
    float a0 = 0.f, a1 = 0.f, a2 = 0.f, a3 = 0.f, a4 = 0.f, a5 = 0.f, a6 = 0.f, a7 = 0.f;
    #pragma unroll 4
    for (int m = 0; m < MM; m++) {
        float w = sc[h * MM + m];
        const float* vp = kbase + (size_t)m * 2 * DMODEL + DMODEL + co;
        float4 v0 = *(const float4*)(vp);
        float4 v1 = *(const float4*)(vp + 4);
        a0 += w*v0.x; a1 += w*v0.y; a2 += w*v0.z; a3 += w*v0.w;
        a4 += w*v1.x; a5 += w*v1.y; a6 += w*v1.z; a7 += w*v1.w;
    }
    float* op = outm + (size_t)row * DMODEL + co;
    *(float4*)(op)     = make_float4(a0, a1, a2, a3);
    *(float4*)(op + 4) = make_float4(a4, a5, a6, a7);
}

__device__ void flash_body(const __half* __restrict__ qkv,
                           __half* __restrict__ outO,
                           char* sm, int fb)
{
    const int tid = threadIdx.x, lane = tid & 31, wm = tid >> 5;
    const int qt = 15 - (fb & 15);
    const int bhh = fb >> 4, b = bhh >> 4, h = bhh & 15;
    const int qbase = qt * 64;
    const size_t srow = (size_t)b * SEQ;

    const uint32_t QA = smem_to_u32(sm);

    const int lrow = tid >> 1;
    const int lh   = (tid & 1) * 32;

    // cp.async producer: K+V tile for iteration kt into buffer buf
    auto issue_kv = [&](int bufi, int kt) {
        const __half* gk = qkv + (srow + kt*64 + lrow) * 3072 + 1024 + h * 64 + lh;
        const uint32_t kd = QA + 9216 + (uint32_t)(bufi * KVBUF) + (uint32_t)(lrow * FROW + lh * 2);
        cp16(kd,      gk);
        cp16(kd + 16, gk + 8);
        cp16(kd + 32, gk + 16);
        cp16(kd + 48, gk + 24);
        const uint32_t vd = kd + 9216;
        cp16(vd,      gk + 1024);
        cp16(vd + 16, gk + 1024 + 8);
        cp16(vd + 32, gk + 1024 + 16);
        cp16(vd + 48, gk + 1024 + 24);
    };

    {   // Q via cp.async too (covered by first WAIT0)
        const __half* gq = qkv + (srow + qbase + lrow) * 3072 + h * 64 + lh;
        const uint32_t qd = QA + (uint32_t)(lrow * FROW + lh * 2);
        cp16(qd,      gq);
        cp16(qd + 16, gq + 8);
        cp16(qd + 32, gq + 16);
        cp16(qd + 48, gq + 24);
    }
    issue_kv(0, 0);
    CP_COMMIT();

    const int r = lane >> 2, q = lane & 3;
    float m0 = -1e30f, m1 = -1e30f, l0 = 0.f, l1 = 0.f;
    float o[8][4];
    #pragma unroll
    for (int i = 0; i < 8; i++) o[i][0]=o[i][1]=o[i][2]=o[i][3]=0.f;

    const uint32_t qaddr0 = QA + (uint32_t)((wm*16 + (lane & 15)) * FROW + ((lane >> 4) & 1) * 16);
    const uint32_t kOff = (uint32_t)((lane & 7) * FROW + ((lane >> 3) & 1) * 16);
    const uint32_t vOff = (uint32_t)((lane & 15) * FROW);

    for (int kt = 0; kt <= qt; kt++) {
        CP_WAIT0();
        __syncthreads();
        // prefetch next tile into the other buffer (overlaps compute below)
        if (kt < qt) issue_kv((kt + 1) & 1, kt + 1);
        CP_COMMIT();

        const uint32_t kvb = QA + 9216 + (uint32_t)((kt & 1) * KVBUF);
        const uint32_t kaddr0 = kvb + kOff;
        const uint32_t vaddr0 = kvb + 9216 + vOff;

        float s[8][4];
        #pragma unroll
        for (int nt = 0; nt < 8; nt++) s[nt][0]=s[nt][1]=s[nt][2]=s[nt][3]=0.f;
        #pragma unroll
        for (int ks = 0; ks < 4; ks++) {
            uint32_t aQ[4];
            ldsm4(aQ, qaddr0 + ks*32);
            uint32_t bK[8][2];
            #pragma unroll
            for (int nt = 0; nt < 8; nt++)
                ldsm2(bK[nt], kaddr0 + (uint32_t)(nt * 8 * FROW + ks * 32));
            #pragma unroll
            for (int nt = 0; nt < 8; nt++) mma16816(s[nt], aQ, bK[nt]);
        }
        #pragma unroll
        for (int nt = 0; nt < 8; nt++) {
            s[nt][0] *= 0.125f; s[nt][1] *= 0.125f;
            s[nt][2] *= 0.125f; s[nt][3] *= 0.125f;
        }

        if (kt == qt) {
            const int r0 = wm*16 + r;
            #pragma unroll
            for (int nt = 0; nt < 8; nt++) {
                const int cb = nt*8 + q*2;
                if (cb     > r0)     s[nt][0] = -1e30f;
                if (cb + 1 > r0)     s[nt][1] = -1e30f;
                if (cb     > r0 + 8) s[nt][2] = -1e30f;
                if (cb + 1 > r0 + 8) s[nt][3] = -1e30f;
            }
        }

        float mx0 = -1e30f, mx1 = -1e30f;
        #pragma unroll
        for (int nt = 0; nt < 8; nt++) {
            mx0 = fmaxf(mx0, fmaxf(s[nt][0], s[nt][1]));
            mx1 = fmaxf(mx1, fmaxf(s[nt][2], s[nt][3]));
        }
        mx0 = fmaxf(mx0, __shfl_xor_sync(0xffffffffu, mx0, 1));
        mx0 = fmaxf(mx0, __shfl_xor_sync(0xffffffffu, mx0, 2));
        mx1 = fmaxf(mx1, __shfl_xor_sync(0xffffffffu, mx1, 1));
        mx1 = fmaxf(mx1, __shfl_xor_sync(0xffffffffu, mx1, 2));
        const float mn0 = fmaxf(m0, mx0);
        const float mn1 = fmaxf(m1, mx1);
        const float al0 = __expf(m0 - mn0), al1 = __expf(m1 - mn1);
        float sum0 = 0.f, sum1 = 0.f;
        #pragma unroll
        for (int nt = 0; nt < 8; nt++) {
            s[nt][0] = __expf(s[nt][0] - mn0);
            s[nt][1] = __expf(s[nt][1] - mn0);
            s[nt][2] = __expf(s[nt][2] - mn1);
            s[nt][3] = __expf(s[nt][3] - mn1);
            sum0 += s[nt][0] + s[nt][1];
            sum1 += s[nt][2] + s[nt][3];
        }
        sum0 += __shfl_xor_sync(0xffffffffu, sum0, 1);
        sum0 += __shfl_xor_sync(0xffffffffu, sum0, 2);
        sum1 += __shfl_xor_sync(0xffffffffu, sum1, 1);
        sum1 += __shfl_xor_sync(0xffffffffu, sum1, 2);
        l0 = al0 * l0 + sum0;
        l1 = al1 * l1 + sum1;
        m0 = mn0; m1 = mn1;
        #pragma unroll
        for (int i = 0; i < 8; i++) {
            o[i][0] *= al0; o[i][1] *= al0; o[i][2] *= al1; o[i][3] *= al1;
        }

        uint32_t aP[4][4];
        #pragma unroll
        for (int ks = 0; ks < 4; ks++) {
            const int n0 = 2*ks, n1 = 2*ks + 1;
            aP[ks][0] = pack_h2(s[n0][0], s[n0][1]);
            aP[ks][1] = pack_h2(s[n0][2], s[n0][3]);
            aP[ks][2] = pack_h2(s[n1][0], s[n1][1]);
            aP[ks][3] = pack_h2(s[n1][2], s[n1][3]);
        }
        #pragma unroll
        for (int ks = 0; ks < 4; ks++) {
            #pragma unroll
            for (int gq4 = 0; gq4 < 2; gq4++) {
                uint32_t bV[4][2];
                #pragma unroll
                for (int j = 0; j < 4; j++)
                    ldsm2t(bV[j], vaddr0 + (uint32_t)(ks * 16 * FROW + (gq4*4 + j) * 16));
                #pragma unroll
                for (int j = 0; j < 4; j++) mma16816(o[gq4*4+j], aP[ks], bV[j]);
            }
        }
    }

    const float i0 = 1.f / l0, i1 = 1.f / l1;
    #pragma unroll
    for (int ntv = 0; ntv < 8; ntv++) {
        const int rg = wm*16 + r, cg = ntv*8 + q*2;
        const size_t o0 = (srow + qbase + rg) * (size_t)DMODEL + h*64 + cg;
        const size_t o1 = o0 + 8 * DMODEL;
        *(uint32_t*)(outO + o0) = pack_h2(o[ntv][0] * i0, o[ntv][1] * i0);
        *(uint32_t*)(outO + o1) = pack_h2(o[ntv][2] * i1, o[ntv][3] * i1);
    }
}

__global__ void __launch_bounds__(128) attn_kernel(
    const __half* __restrict__ qkv, const float* __restrict__ mkv,
    float* __restrict__ outm, __half* __restrict__ outO)
{
    extern __shared__ char sm[];
    if (blockIdx.x < 512) {
        flash_body(qkv, outO, sm, blockIdx.x);
    } else {
        memattn_body(qkv, mkv, outm, blockIdx.x - 512);
    }
}

// ------------------------------ launcher ------------------------------------
extern "C" void kernel_launch(void* const* d_in, const int* in_sizes, int n_in,
                              void* d_out, int out_size)
{
    (void)in_sizes; (void)n_in; (void)out_size;
    const float* prev  = (const float*)d_in[0];
    const float* memkv = (const float*)d_in[1];
    const float* gval  = (const float*)d_in[2];
    const float* ln1g  = (const float*)d_in[3];
    const float* ln1b  = (const float*)d_in[4];
    const float* attnw = (const float*)d_in[5];
    const float* attnb = (const float*)d_in[6];
    const float* cprw  = (const float*)d_in[7];
    const float* cprb  = (const float*)d_in[8];
    const float* ln2g  = (const float*)d_in[9];
    const float* ln2b  = (const float*)d_in[10];
    const float* fcw   = (const float*)d_in[11];
    const float* fcb   = (const float*)d_in[12];
    const float* pw    = (const float*)d_in[13];
    const float* pb    = (const float*)d_in[14];
    float* out = (float*)d_out;

    float *mem, *hid;
    __half *qkv, *h1, *att, *h2, *ff, *wq, *wp, *wf, *wo;
    cudaGetSymbolAddress((void**)&qkv, g_qkv);
    cudaGetSymbolAddress((void**)&mem, g_mem);
    cudaGetSymbolAddress((void**)&hid, g_hid);
    cudaGetSymbolAddress((void**)&h1,  g_h1);
    cudaGetSymbolAddress((void**)&att, g_att);
    cudaGetSymbolAddress((void**)&h2,  g_h2);
    cudaGetSymbolAddress((void**)&ff,  g_ff);
    cudaGetSymbolAddress((void**)&wq,  g_wq);
    cudaGetSymbolAddress((void**)&wp,  g_wp);
    cudaGetSymbolAddress((void**)&wf,  g_wf);
    cudaGetSymbolAddress((void**)&wo,  g_wo);

    cudaFuncSetAttribute(attn_kernel, cudaFuncAttributeMaxDynamicSharedMemorySize, FLASH_SMEM);
    cudaFuncSetAttribute(gemm_mma_kernel<4>, cudaFuncAttributeMaxDynamicSharedMemorySize, GEMM_SMEM);
    cudaFuncSetAttribute(gemm_mma_kernel<2>, cudaFuncAttributeMaxDynamicSharedMemorySize, GEMM_SMEM);
    cudaFuncSetAttribute(gemm_mma64_kernel<1>, cudaFuncAttributeMaxDynamicSharedMemorySize, GEMM64_SMEM);
    cudaFuncSetAttribute(gemm_mma64_kernel<3>, cudaFuncAttributeMaxDynamicSharedMemorySize, GEMM64_SMEM);

    // 1) prep: LN1 + all weight converts (fused, consolidated)
    prep_kernel<<<2048 + 768 + 256 + 1024 + 1024, 256>>>(prev, ln1g, ln1b, h1,
        attnw, wq, cprw, wp, fcw, wf, pw, wo);
    // 2) qkv = h1 @ c_attn + b (fp16)
    gemm_mma_kernel<4><<<dim3(24, 16), 256, GEMM_SMEM>>>(h1, wq, attnb,
        nullptr, qkv, ROWS, 3*DMODEL, DMODEL, nullptr, nullptr, nullptr);
    // 3) fused flash-mma (cp.async pipelined) + memattn
    attn_kernel<<<512 + 2048, 128, FLASH_SMEM>>>(qkv, memkv, mem, att);
    // 4) hid = (1-g)*(att@c_proj+b) + g*mem + prev   (64x128, R13 config)
    gemm_mma64_kernel<1><<<dim3(8, 32), 128, GEMM64_SMEM>>>(att, wp, cprb,
        hid, nullptr, ROWS, DMODEL, DMODEL, mem, prev, gval);
    // 5) LN2 -> h2
    prep_kernel<<<2048, 256>>>(hid, ln2g, ln2b, h2,
        nullptr, nullptr, nullptr, nullptr, nullptr, nullptr, nullptr, nullptr);
    // 6) ff = gelu(h2 @ fc + b) -> fp16
    gemm_mma_kernel<2><<<dim3(32, 16), 256, GEMM_SMEM>>>(h2, wf, fcb,
        nullptr, ff, ROWS, 4*DMODEL, DMODEL, nullptr, nullptr, nullptr);
    // 7) out = ff @ proj + b + hid   (64x128, R13 config)
    gemm_mma64_kernel<3><<<dim3(8, 32), 128, GEMM64_SMEM>>>(ff, wo, pb,
        out, nullptr, ROWS, DMODEL, 4*DMODEL, hid, nullptr, nullptr);
}

// round 16
// speedup vs baseline: 1.1136x; 1.0102x over previous
#include <cuda_runtime.h>
#include <cuda_fp16.h>
#include <cstdint>

#define BS_    2
#define SEQ    1024
#define DMODEL 1024
#define NH     16
#define HD     64
#define MM     32
#define ROWS   (BS_*SEQ)

// ---------------- scratch (device globals) ----------------
__device__ __half g_qkv[ROWS*3*DMODEL];
__device__ float g_mem[ROWS*DMODEL];
__device__ float g_hid[ROWS*DMODEL];
__device__ __half g_h1 [ROWS*DMODEL];
__device__ __half g_att[ROWS*DMODEL];
__device__ __half g_h2 [ROWS*DMODEL];
__device__ __half g_ff [ROWS*4*DMODEL];
__device__ __half g_wq[DMODEL*3*DMODEL];
__device__ __half g_wp[DMODEL*DMODEL];
__device__ __half g_wf[DMODEL*4*DMODEL];
__device__ __half g_wo[4*DMODEL*DMODEL];

// ---------------- helpers ----------------
__device__ __forceinline__ uint32_t smem_to_u32(const void* p) {
    uint32_t a;
    asm("{ .reg .u64 t; cvta.to.shared.u64 t, %1; cvt.u32.u64 %0, t; }" : "=r"(a) : "l"(p));
    return a;
}
__device__ __forceinline__ void cp16(uint32_t s, const void* g) {
    asm volatile("cp.async.cg.shared.global [%0], [%1], 16;" :: "r"(s), "l"(g));
}
#define CP_COMMIT() asm volatile("cp.async.commit_group;" ::: "memory")
#define CP_WAIT1()  asm volatile("cp.async.wait_group 1;" ::: "memory")
#define CP_WAIT0()  asm volatile("cp.async.wait_group 0;" ::: "memory")

__device__ __forceinline__ void ldsm4(uint32_t* r, uint32_t addr) {
    asm volatile("ldmatrix.sync.aligned.m8n8.x4.shared.b16 {%0,%1,%2,%3}, [%4];"
        : "=r"(r[0]), "=r"(r[1]), "=r"(r[2]), "=r"(r[3]) : "r"(addr));
}
__device__ __forceinline__ void ldsm2(uint32_t* r, uint32_t addr) {
    asm volatile("ldmatrix.sync.aligned.m8n8.x2.shared.b16 {%0,%1}, [%2];"
        : "=r"(r[0]), "=r"(r[1]) : "r"(addr));
}
__device__ __forceinline__ void ldsm2t(uint32_t* r, uint32_t addr) {
    asm volatile("ldmatrix.sync.aligned.m8n8.x2.trans.shared.b16 {%0,%1}, [%2];"
        : "=r"(r[0]), "=r"(r[1]) : "r"(addr));
}
__device__ __forceinline__ void mma16816(float* d, const uint32_t* a, const uint32_t* b) {
    asm volatile(
      "mma.sync.aligned.m16n8k16.row.col.f32.f16.f16.f32 "
      "{%0,%1,%2,%3}, {%4,%5,%6,%7}, {%8,%9}, {%0,%1,%2,%3};"
      : "+f"(d[0]), "+f"(d[1]), "+f"(d[2]), "+f"(d[3])
      : "r"(a[0]), "r"(a[1]), "r"(a[2]), "r"(a[3]), "r"(b[0]), "r"(b[1]));
}

__device__ __forceinline__ float gelu_new(float x) {
    float x3 = x * x * x;
    float t  = tanhf(0.7978845608028654f * (x + 0.044715f * x3));
    return 0.5f * x * (1.f + t);
}
__device__ __forceinline__ uint32_t pack_h2(float x, float y) {
    __half2 t = __floats2half2_rn(x, y);
    return *reinterpret_cast<uint32_t*>(&t);
}

// ---------------- weight convert bodies ----------------
// 256-thread variant (prep kernel)
__device__ void wconv_body(float* shm,
    const float* __restrict__ W, __half* __restrict__ hi,
    int K, int N, int bx, int by)
{
    float (*s)[33] = (float(*)[33])shm;
    const int tx = threadIdx.x & 31, ty = threadIdx.x >> 5;
    const int n0 = bx * 32, k0 = by * 32;
    #pragma unroll
    for (int i = 0; i < 4; i++)
        s[ty + 8*i][tx] = W[(size_t)(k0 + ty + 8*i) * N + n0 + tx];
    __syncthreads();
    #pragma unroll
    for (int i = 0; i < 4; i++) {
        int n = ty + 8*i;
        hi[(size_t)(n0 + n) * K + k0 + tx] = __float2half(s[tx][n]);
    }
    __syncthreads();
}
__device__ void wconv4_body(float* shm,
    const float* __restrict__ W, __half* __restrict__ hi,
    int K, int N, int bxg, int by)
{
    #pragma unroll
    for (int t = 0; t < 4; t++)
        wconv_body(shm, W, hi, K, N, bxg * 4 + t, by);
}

// 128-thread variant (ride-along in attn kernel)
__device__ void wconv_body128(float* shm,
    const float* __restrict__ W, __half* __restrict__ hi,
    int K, int N, int bx, int by)
{
    float (*s)[33] = (float(*)[33])shm;
    const int tx = threadIdx.x & 31, ty = threadIdx.x >> 5;  // ty 0..3
    const int n0 = bx * 32, k0 = by * 32;
    #pragma unroll
    for (int i = 0; i < 8; i++)
        s[ty + 4*i][tx] = W[(size_t)(k0 + ty + 4*i) * N + n0 + tx];
    __syncthreads();
    #pragma unroll
    for (int i = 0; i < 8; i++) {
        int n = ty + 4*i;
        hi[(size_t)(n0 + n) * K + k0 + tx] = __float2half(s[tx][n]);
    }
    __syncthreads();
}
__device__ void wconv4_body128(float* shm,
    const float* __restrict__ W, __half* __restrict__ hi,
    int K, int N, int bxg, int by)
{
    #pragma unroll
    for (int t = 0; t < 4; t++)
        wconv_body128(shm, W, hi, K, N, bxg * 4 + t, by);
}

__device__ void ln_body(float* shm, int row,
    const float* __restrict__ x, const float* __restrict__ g,
    const float* __restrict__ b, __half* __restrict__ y)
{
    const int tid = threadIdx.x;
    float* rs = shm; float* rs2 = shm + 8;
    const float* xr = x + (size_t)row * DMODEL;
    float4 v = *(const float4*)(xr + tid * 4);
    float s  = v.x + v.y + v.z + v.w;
    float s2 = v.x*v.x + v.y*v.y + v.z*v.z + v.w*v.w;
    #pragma unroll
    for (int o = 16; o; o >>= 1) {
        s  += __shfl_xor_sync(0xffffffffu, s,  o);
        s2 += __shfl_xor_sync(0xffffffffu, s2, o);
    }
    const int w = tid >> 5, l = tid & 31;
    if (!l) { rs[w] = s; rs2[w] = s2; }
    __syncthreads();
    s = 0.f; s2 = 0.f;
    #pragma unroll
    for (int i = 0; i < 8; i++) { s += rs[i]; s2 += rs2[i]; }
    const float mean = s * (1.f / DMODEL);
    const float var  = s2 * (1.f / DMODEL) - mean * mean;
    const float rstd = rsqrtf(var + 1e-5f);
    const int c = tid * 4;
    float4 gg = *(const float4*)(g + c);
    float4 bb = *(const float4*)(b + c);
    float4 o;
    o.x = (v.x - mean) * rstd * gg.x + bb.x;
    o.y = (v.y - mean) * rstd * gg.y + bb.y;
    o.z = (v.z - mean) * rstd * gg.z + bb.z;
    o.w = (v.w - mean) * rstd * gg.w + bb.w;
    uint2 hh;
    hh.x = pack_h2(o.x, o.y); hh.y = pack_h2(o.z, o.w);
    *(uint2*)(y + (size_t)row * DMODEL + c) = hh;
}

// prep: LN (2048 blocks) + optional attnw wconv4 (768 blocks)
__global__ void __launch_bounds__(256) prep_kernel(
    const float* x, const float* lng, const float* lnb, __half* y,
    const float* attnw, __half* wq)
{
    __shared__ float shm[32*33];
    int idx = blockIdx.x;
    if (idx < 2048) { ln_body(shm, idx, x, lng, lnb, y); return; }
    idx -= 2048;
    wconv4_body(shm, attnw, wq, 1024, 3072, idx % 24, idx / 24);
}

// ---------------- epilogue (shared) -----------------------------------------
template<int EPI>
__device__ __forceinline__ void gemm_epilogue_elem(
    float v0, float v1, const float2 bb, size_t o,
    float* Cf, __half* Ch,
    const float* aux1, const float* aux2, float g)
{
    v0 += bb.x; v1 += bb.y;
    if (EPI == 1) {
        float2 a1 = *(const float2*)(aux1 + o);
        float2 a2 = *(const float2*)(aux2 + o);
        v0 = (1.f - g) * v0 + g * a1.x + a2.x;
        v1 = (1.f - g) * v1 + g * a1.y + a2.y;
    }
    if (EPI == 3) {
        float2 a1 = *(const float2*)(aux1 + o);
        v0 += a1.x; v1 += a1.y;
    }
    if (EPI == 2) {
        v0 = gelu_new(v0); v1 = gelu_new(v1);
        *(uint32_t*)(Ch + o) = pack_h2(v0, v1);
    } else if (EPI == 4) {
        *(uint32_t*)(Ch + o) = pack_h2(v0, v1);
    } else {
        *(float2*)(Cf + o) = make_float2(v0, v1);
    }
}

// ---------------- GEMM 128x128 tile, fp16, K-chunk 64 ------------------------
#define AB_     8192
#define GSTAGE  (4*AB_)                 // 32768
#define GEMM_SMEM (3*GSTAGE)            // 98304

template<int EPI>
__global__ void __launch_bounds__(256, 2) gemm_mma_kernel(
    const __half* __restrict__ A, const __half* __restrict__ B,
    const float* __restrict__ bias,
    float* __restrict__ Cf, __half* __restrict__ Ch,
    int M, int N, int K,
    const float* __restrict__ aux1, const float* __restrict__ aux2,
    const float* __restrict__ gp)
{
    extern __shared__ char smp[];
    const uint32_t sb = smem_to_u32(smp);
    const int tid = threadIdx.x;
    const int wid = tid >> 5, lane = tid & 31;
    const int wm = wid & 1, wn = wid >> 1;
    const int bm = blockIdx.y, bn = blockIdx.x;
    const int NC = K >> 6;

    const size_t Abase = (size_t)bm * 128 * K;
    const size_t Bbase = (size_t)bn * 128 * K;

    float acc[4][4][4];
    #pragma unroll
    for (int i = 0; i < 4; i++)
        #pragma unroll
        for (int j = 0; j < 4; j++)
            #pragma unroll
            for (int x = 0; x < 4; x++) acc[i][j][x] = 0.f;

    const int crow = tid >> 2;
    const int cq   = tid & 3;
    const uint32_t so0 = (uint32_t)(crow * 64 + ((cq ^ (crow & 3)) << 4));
    const uint32_t so1 = so0 + 64 * 64;

    auto issue = [&](int buf, int kt) {
        const int k0 = kt << 6;
        const uint32_t sbase = sb + buf * GSTAGE;
        const size_t g0 = (size_t)crow * K + k0 + cq * 8;
        const size_t g1 = g0 + (size_t)64 * K;
        #pragma unroll
        for (int sl = 0; sl < 2; sl++) {
            cp16(sbase + sl*AB_ + so0,          A + Abase + g0 + sl*32);
            cp16(sbase + sl*AB_ + so1,          A + Abase + g1 + sl*32);
            cp16(sbase + (2+sl)*AB_ + so0,      B + Bbase + g0 + sl*32);
            cp16(sbase + (2+sl)*AB_ + so1,      B + Bbase + g1 + sl*32);
        }
    };

    issue(0, 0); CP_COMMIT();
    issue(1, 1); CP_COMMIT();

    const uint32_t rowA = (uint32_t)(wm * 64 + (lane & 15));
    const uint32_t qa   = (uint32_t)(lane >> 4);
    const uint32_t r3a  = rowA & 3;
    const uint32_t aBase = rowA * 64;
    const uint32_t rowB = (uint32_t)(wn * 32 + (lane & 7));
    const uint32_t qb   = (uint32_t)((lane >> 3) & 1);
    const uint32_t r3b  = rowB & 3;
    const uint32_t bBase = rowB * 64;

    int buf = 0;
    for (int c = 0; c < NC; c++) {
        CP_WAIT1();
        __syncthreads();
        if (c + 2 < NC) { int nb = buf + 2; if (nb >= 3) nb -= 3; issue(nb, c + 2); }
        CP_COMMIT();

        const uint32_t s0 = sb + buf * GSTAGE;
        #pragma unroll
        for (int sl = 0; sl < 2; sl++) {
            const uint32_t sA = s0 + sl*AB_;
            const uint32_t sB = s0 + (2+sl)*AB_;
            #pragma unroll
            for (int ks = 0; ks < 2; ks++) {
                uint32_t bfr[4][2];
                const uint32_t qpb = ((qb + 2*ks) ^ r3b) << 4;
                #pragma unroll
                for (int nt = 0; nt < 4; nt++)
                    ldsm2(bfr[nt], sB + bBase + (uint32_t)(nt * 512) + qpb);
                const uint32_t qpa = ((qa + 2*ks) ^ r3a) << 4;
                #pragma unroll
                for (int mt = 0; mt < 4; mt++) {
                    uint32_t a[4];
                    ldsm4(a, sA + aBase + (uint32_t)(mt * 1024) + qpa);
                    #pragma unroll
                    for (int nt = 0; nt < 4; nt++) mma16816(acc[mt][nt], a, bfr[nt]);
                }
            }
        }
        buf++; if (buf >= 3) buf = 0;
    }

    const int r = lane >> 2, q = lane & 3;
    const float g = (EPI == 1) ? *gp : 0.f;
    #pragma unroll
    for (int mt = 0; mt < 4; mt++) {
        #pragma unroll
        for (int nt = 0; nt < 4; nt++) {
            const int col = bn * 128 + wn * 32 + nt * 8 + q * 2;
            const float2 bb = *(const float2*)(bias + col);
            #pragma unroll
            for (int hh = 0; hh < 2; hh++) {
                const int row = bm * 128 + wm * 64 + mt * 16 + r + hh * 8;
                gemm_epilogue_elem<EPI>(acc[mt][nt][hh*2], acc[mt][nt][hh*2+1], bb,
                    (size_t)row * N + col, Cf, Ch, aux1, aux2, g);
            }
        }
    }
}

// ---------------- GEMM 64x128 tile, fp16, K-chunk 64 -------------------------
#define A64_      4096
#define B64_      8192
#define GSTAGE64  (2*A64_ + 2*B64_)     // 24576
#define GEMM64_SMEM (3*GSTAGE64)        // 73728

template<int EPI>
__global__ void __launch_bounds__(128, 3) gemm_mma64_kernel(
    const __half* __restrict__ A, const __half* __restrict__ B,
    const float* __restrict__ bias,
    float* __restrict__ Cf, __half* __restrict__ Ch,
    int M, int N, int K,
    const float* __restrict__ aux1, const float* __restrict__ aux2,
    const float* __restrict__ gp)
{
    extern __shared__ char smp[];
    const uint32_t sb = smem_to_u32(smp);
    const int tid = threadIdx.x;
    const int wn = tid >> 5, lane = tid & 31;
    const int bm = blockIdx.y, bn = blockIdx.x;
    const int NC = K >> 6;

    const size_t Abase = (size_t)bm * 64 * K;
    const size_t Bbase = (size_t)bn * 128 * K;

    float acc[4][4][4];
    #pragma unroll
    for (int i = 0; i < 4; i++)
        #pragma unroll
        for (int j = 0; j < 4; j++)
            #pragma unroll
            for (int x = 0; x < 4; x++) acc[i][j][x] = 0.f;

    const int crow = tid >> 2;
    const int cq   = tid & 3;
    const uint32_t soA = (uint32_t)(crow * 64 + ((cq ^ (crow & 3)) << 4));

    auto issue = [&](int buf, int kt) {
        const int k0 = kt << 6;
        const uint32_t sbase = sb + buf * GSTAGE64;
        const size_t gc = (size_t)crow * K + k0 + cq * 8;
        #pragma unroll
        for (int sl = 0; sl < 2; sl++) {
            cp16(sbase + sl*A64_ + soA,        A + Abase + gc + sl*32);
            cp16(sbase + sl*A64_ + soA + 2048, A + Abase + gc + sl*32 + (size_t)32 * K);
            #pragma unroll
            for (int j = 0; j < 4; j++)
                cp16(sbase + 2*A64_ + sl*B64_ + soA + j*2048,
                     B + Bbase + gc + sl*32 + (size_t)(32 * j) * K);
        }
    };

    issue(0, 0); CP_COMMIT();
    issue(1, 1); CP_COMMIT();

    const uint32_t rowA = (uint32_t)(lane & 15);
    const uint32_t qa   = (uint32_t)(lane >> 4);
    const uint32_t r3a  = rowA & 3;
    const uint32_t aBase = rowA * 64;
    const uint32_t rowB = (uint32_t)(wn * 32 + (lane & 7));
    const uint32_t qb   = (uint32_t)((lane >> 3) & 1);
    const uint32_t r3b  = rowB & 3;
    const uint32_t bBase = rowB * 64;

    int buf = 0;
    for (int c = 0; c < NC; c++) {
        CP_WAIT1();
        __syncthreads();
        if (c + 2 < NC) { int nb = buf + 2; if (nb >= 3) nb -= 3; issue(nb, c + 2); }
        CP_COMMIT();

        const uint32_t s0 = sb + buf * GSTAGE64;
        #pragma unroll
        for (int sl = 0; sl < 2; sl++) {
            const uint32_t sA = s0 + sl*A64_;
            const uint32_t sB = s0 + 2*A64_ + sl*B64_;
            #pragma unroll
            for (int ks = 0; ks < 2; ks++) {
                uint32_t bfr[4][2];
                const uint32_t qpb = ((qb + 2*ks) ^ r3b) << 4;
                #pragma unroll
                for (int nt = 0; nt < 4; nt++)
                    ldsm2(bfr[nt], sB + bBase + (uint32_t)(nt * 512) + qpb);
                const uint32_t qpa = ((qa + 2*ks) ^ r3a) << 4;
                #pragma unroll
                for (int mt = 0; mt < 4; mt++) {
                    uint32_t a[4];
                    ldsm4(a, sA + aBase + (uint32_t)(mt * 1024) + qpa);
                    #pragma unroll
                    for (int nt = 0; nt < 4; nt++) mma16816(acc[mt][nt], a, bfr[nt]);
                }
            }
        }
        buf++; if (buf >= 3) buf = 0;
    }

    const int r = lane >> 2, q = lane & 3;
    const float g = (EPI == 1) ? *gp : 0.f;
    #pragma unroll
    for (int mt = 0; mt < 4; mt++) {
        #pragma unroll
        for (int nt = 0; nt < 4; nt++) {
            const int col = bn * 128 + wn * 32 + nt * 8 + q * 2;
            const float2 bb = *(const float2*)(bias + col);
            #pragma unroll
            for (int hh = 0; hh < 2; hh++) {
                const int row = bm * 64 + mt * 16 + r + hh * 8;
                gemm_epilogue_elem<EPI>(acc[mt][nt][hh*2], acc[mt][nt][hh*2+1], bb,
                    (size_t)row * N + col, Cf, Ch, aux1, aux2, g);
            }
        }
    }
}

// ---------------- fused attention + ride-along wconv (128 threads) ----------
// blocks: [0,512) flash | [512,2560) memattn | [2560,4864) wconv wp/wf/wo
#define FROW 144
#define KVBUF (2*9216)
#define FLASH_SMEM (9216 + 2*KVBUF)

__device__ void memattn_body(const __half* __restrict__ qkv,
                             const float* __restrict__ mkv,
                             float* __restrict__ outm, int row)
{
    const int tid = threadIdx.x;
    const int h = tid >> 3, t8 = tid & 7;
    __shared__ float sc[NH * MM];
    const int co = h * 64 + t8 * 8;
    uint4 qraw = *(const uint4*)(qkv + (size_t)row * 3072 + co);
    float qv[8];
    {
        __half2* qh = (__half2*)&qraw;
        #pragma unroll
        for (int i = 0; i < 4; i++) {
            qv[2*i]   = __low2float(qh[i])  * 0.125f;
            qv[2*i+1] = __high2float(qh[i]) * 0.125f;
        }
    }
    const float* kbase = mkv + (size_t)row * MM * 2 * DMODEL;
    #pragma unroll 4
    for (int m = 0; m < MM; m++) {
        const float* kp = kbase + (size_t)m * 2 * DMODEL + co;
        float4 k0 = *(const float4*)(kp);
        float4 k1 = *(const float4*)(kp + 4);
        float d = qv[0]*k0.x + qv[1]*k0.y + qv[2]*k0.z + qv[3]*k0.w
                + qv[4]*k1.x + qv[5]*k1.y + qv[6]*k1.z + qv[7]*k1.w;
        #pragma unroll
        for (int o = 4; o; o >>= 1) d += __shfl_xor_sync(0xffffffffu, d, o);
        if (t8 == 0) sc[h * MM + m] = d;
    }
    __syncthreads();
    if (tid < NH) {
        float mx = -1e30f;
        #pragma unroll
        for (int m = 0; m < MM; m++) mx = fmaxf(mx, sc[tid * MM + m]);
        float s = 0.f;
        #pragma unroll
        for (int m = 0; m < MM; m++) {
            float e = __expf(sc[tid * MM + m] - mx);
            sc[tid * MM + m] = e; s += e;
        }
        float inv = 1.f / s;
        #pragma unroll
        for (int m = 0; m < MM; m++) sc[tid * MM + m] *= inv;
    }
    __syncthreads();
    float a0 = 0.f, a1 = 0.f, a2 = 0.f, a3 = 0.f, a4 = 0.f, a5 = 0.f, a6 = 0.f, a7 = 0.f;
    #pragma unroll 4
    for (int m = 0; m < MM; m++) {
        float w = sc[h * MM + m];
        const float* vp = kbase + (size_t)m * 2 * DMODEL + DMODEL + co;
        float4 v0 = *(const float4*)(vp);
        float4 v1 = *(const float4*)(vp + 4);
        a0 += w*v0.x; a1 += w*v0.y; a2 += w*v0.z; a3 += w*v0.w;
        a4 += w*v1.x; a5 += w*v1.y; a6 += w*v1.z; a7 += w*v1.w;
    }
    float* op = outm + (size_t)row * DMODEL + co;
    *(float4*)(op)     = make_float4(a0, a1, a2, a3);
    *(float4*)(op + 4) = make_float4(a4, a5, a6, a7);
}

__device__ void flash_body(const __half* __restrict__ qkv,
                           __half* __restrict__ outO,
                           char* sm, int fb)
{
    const int tid = threadIdx.x, lane = tid & 31, wm = tid >> 5;
    const int qt = 15 - (fb & 15);
    const int bhh = fb >> 4, b = bhh >> 4, h = bhh & 15;
    const int qbase = qt * 64;
    const size_t srow = (size_t)b * SEQ;

    const uint32_t QA = smem_to_u32(sm);

    const int lrow = tid >> 1;
    const int lh   = (tid & 1) * 32;

    auto issue_kv = [&](int bufi, int kt) {
        const __half* gk = qkv + (srow + kt*64 + lrow) * 3072 + 1024 + h * 64 + lh;
        const uint32_t kd = QA + 9216 + (uint32_t)(bufi * KVBUF) + (uint32_t)(lrow * FROW + lh * 2);
        cp16(kd,      gk);
        cp16(kd + 16, gk + 8);
        cp16(kd + 32, gk + 16);
        cp16(kd + 48, gk + 24);
        const uint32_t vd = kd + 9216;
        cp16(vd,      gk + 1024);
        cp16(vd + 16, gk + 1024 + 8);
        cp16(vd + 32, gk + 1024 + 16);
        cp16(vd + 48, gk + 1024 + 24);
    };

    {
        const __half* gq = qkv + (srow + qbase + lrow) * 3072 + h * 64 + lh;
        const uint32_t qd = QA + (uint32_t)(lrow * FROW + lh * 2);
        cp16(qd,      gq);
        cp16(qd + 16, gq + 8);
        cp16(qd + 32, gq + 16);
        cp16(qd + 48, gq + 24);
    }
    issue_kv(0, 0);
    CP_COMMIT();

    const int r = lane >> 2, q = lane & 3;
    float m0 = -1e30f, m1 = -1e30f, l0 = 0.f, l1 = 0.f;
    float o[8][4];
    #pragma unroll
    for (int i = 0; i < 8; i++) o[i][0]=o[i][1]=o[i][2]=o[i][3]=0.f;

    const uint32_t qaddr0 = QA + (uint32_t)((wm*16 + (lane & 15)) * FROW + ((lane >> 4) & 1) * 16);
    const uint32_t kOff = (uint32_t)((lane & 7) * FROW + ((lane >> 3) & 1) * 16);
    const uint32_t vOff = (uint32_t)((lane & 15) * FROW);

    for (int kt = 0; kt <= qt; kt++) {
        CP_WAIT0();
        __syncthreads();
        if (kt < qt) issue_kv((kt + 1) & 1, kt + 1);
        CP_COMMIT();

        const uint32_t kvb = QA + 9216 + (uint32_t)((kt & 1) * KVBUF);
        const uint32_t kaddr0 = kvb + kOff;
        const uint32_t vaddr0 = kvb + 9216 + vOff;

        float s[8][4];
        #pragma unroll
        for (int nt = 0; nt < 8; nt++) s[nt][0]=s[nt][1]=s[nt][2]=s[nt][3]=0.f;
        #pragma unroll
        for (int ks = 0; ks < 4; ks++) {
            uint32_t aQ[4];
            ldsm4(aQ, qaddr0 + ks*32);
            uint32_t bK[8][2];
            #pragma unroll
            for (int nt = 0; nt < 8; nt++)
                ldsm2(bK[nt], kaddr0 + (uint32_t)(nt * 8 * FROW + ks * 32));
            #pragma unroll
            for (int nt = 0; nt < 8; nt++) mma16816(s[nt], aQ, bK[nt]);
        }
        #pragma unroll
        for (int nt = 0; nt < 8; nt++) {
            s[nt][0] *= 0.125f; s[nt][1] *= 0.125f;
            s[nt][2] *= 0.125f; s[nt][3] *= 0.125f;
        }

        if (kt == qt) {
            const int r0 = wm*16 + r;
            #pragma unroll
            for (int nt = 0; nt < 8; nt++) {
                const int cb = nt*8 + q*2;
                if (cb     > r0)     s[nt][0] = -1e30f;
                if (cb + 1 > r0)     s[nt][1] = -1e30f;
                if (cb     > r0 + 8) s[nt][2] = -1e30f;
                if (cb + 1 > r0 + 8) s[nt][3] = -1e30f;
            }
        }

        float mx0 = -1e30f, mx1 = -1e30f;
        #pragma unroll
        for (int nt = 0; nt < 8; nt++) {
            mx0 = fmaxf(mx0, fmaxf(s[nt][0], s[nt][1]));
            mx1 = fmaxf(mx1, fmaxf(s[nt][2], s[nt][3]));
        }
        mx0 = fmaxf(mx0, __shfl_xor_sync(0xffffffffu, mx0, 1));
        mx0 = fmaxf(mx0, __shfl_xor_sync(0xffffffffu, mx0, 2));
        mx1 = fmaxf(mx1, __shfl_xor_sync(0xffffffffu, mx1, 1));
        mx1 = fmaxf(mx1, __shfl_xor_sync(0xffffffffu, mx1, 2));
        const float mn0 = fmaxf(m0, mx0);
        const float mn1 = fmaxf(m1, mx1);
        const float al0 = __expf(m0 - mn0), al1 = __expf(m1 - mn1);
        float sum0 = 0.f, sum1 = 0.f;
        #pragma unroll
        for (int nt = 0; nt < 8; nt++) {
            s[nt][0] = __expf(s[nt][0] - mn0);
            s[nt][1] = __expf(s[nt][1] - mn0);
            s[nt][2] = __expf(s[nt][2] - mn1);
            s[nt][3] = __expf(s[nt][3] - mn1);
            sum0 += s[nt][0] + s[nt][1];
            sum1 += s[nt][2] + s[nt][3];
        }
        sum0 += __shfl_xor_sync(0xffffffffu, sum0, 1);
        sum0 += __shfl_xor_sync(0xffffffffu, sum0, 2);
        sum1 += __shfl_xor_sync(0xffffffffu, sum1, 1);
        sum1 += __shfl_xor_sync(0xffffffffu, sum1, 2);
        l0 = al0 * l0 + sum0;
        l1 = al1 * l1 + sum1;
        m0 = mn0; m1 = mn1;
        #pragma unroll
        for (int i = 0; i < 8; i++) {
            o[i][0] *= al0; o[i][1] *= al0; o[i][2] *= al1; o[i][3] *= al1;
        }

        uint32_t aP[4][4];
        #pragma unroll
        for (int ks = 0; ks < 4; ks++) {
            const int n0 = 2*ks, n1 = 2*ks + 1;
            aP[ks][0] = pack_h2(s[n0][0], s[n0][1]);
            aP[ks][1] = pack_h2(s[n0][2], s[n0][3]);
            aP[ks][2] = pack_h2(s[n1][0], s[n1][1]);
            aP[ks][3] = pack_h2(s[n1][2], s[n1][3]);
        }
        #pragma unroll
        for (int ks = 0; ks < 4; ks++) {
            #pragma unroll
            for (int gq4 = 0; gq4 < 2; gq4++) {
                uint32_t bV[4][2];
                #pragma unroll
                for (int j = 0; j < 4; j++)
                    ldsm2t(bV[j], vaddr0 + (uint32_t)(ks * 16 * FROW + (gq4*4 + j) * 16));
                #pragma unroll
                for (int j = 0; j < 4; j++) mma16816(o[gq4*4+j], aP[ks], bV[j]);
            }
        }
    }

    const float i0 = 1.f / l0, i1 = 1.f / l1;
    #pragma unroll
    for (int ntv = 0; ntv < 8; ntv++) {
        const int rg = wm*16 + r, cg = ntv*8 + q*2;
        const size_t o0 = (srow + qbase + rg) * (size_t)DMODEL + h*64 + cg;
        const size_t o1 = o0 + 8 * DMODEL;
        *(uint32_t*)(outO + o0) = pack_h2(o[ntv][0] * i0, o[ntv][1] * i0);
        *(uint32_t*)(outO + o1) = pack_h2(o[ntv][2] * i1, o[ntv][3] * i1);
    }
}

__global__ void __launch_bounds__(128) attn_kernel(
    const __half* __restrict__ qkv, const float* __restrict__ mkv,
    float* __restrict__ outm, __half* __restrict__ outO,
    const float* __restrict__ cprw, __half* __restrict__ wp,
    const float* __restrict__ fcw,  __half* __restrict__ wf,
    const float* __restrict__ pw,   __half* __restrict__ wo)
{
    extern __shared__ char sm[];
    int idx = blockIdx.x;
    if (idx < 512) { flash_body(qkv, outO, sm, idx); return; }
    idx -= 512;
    if (idx < 2048) { memattn_body(qkv, mkv, outm, idx); return; }
    idx -= 2048;
    float* shm = (float*)sm;
    if (idx < 256)  { wconv4_body128(shm, cprw, wp, 1024, 1024, idx % 8, idx / 8); return; }
    idx -= 256;
    if (idx < 1024) { wconv4_body128(shm, fcw, wf, 1024, 4096, idx % 32, idx / 32); return; }
    idx -= 1024;
    wconv4_body128(shm, pw, wo, 4096, 1024, idx % 8, idx / 8);
}

// ------------------------------ launcher ------------------------------------
extern "C" void kernel_launch(void* const* d_in, const int* in_sizes, int n_in,
                              void* d_out, int out_size)
{
    (void)in_sizes; (void)n_in; (void)out_size;
    const float* prev  = (const float*)d_in[0];
    const float* memkv = (const float*)d_in[1];
    const float* gval  = (const float*)d_in[2];
    const float* ln1g  = (const float*)d_in[3];
    const float* ln1b  = (const float*)d_in[4];
    const float* attnw = (const float*)d_in[5];
    const float* attnb = (const float*)d_in[6];
    const float* cprw  = (const float*)d_in[7];
    const float* cprb  = (const float*)d_in[8];
    const float* ln2g  = (const float*)d_in[9];
    const float* ln2b  = (const float*)d_in[10];
    const float* fcw   = (const float*)d_in[11];
    const float* fcb   = (const float*)d_in[12];
    const float* pw    = (const float*)d_in[13];
    const float* pb    = (const float*)d_in[14];
    float* out = (float*)d_out;

    float *mem, *hid;
    __half *qkv, *h1, *att, *h2, *ff, *wq, *wp, *wf, *wo;
    cudaGetSymbolAddress((void**)&qkv, g_qkv);
    cudaGetSymbolAddress((void**)&mem, g_mem);
    cudaGetSymbolAddress((void**)&hid, g_hid);
    cudaGetSymbolAddress((void**)&h1,  g_h1);
    cudaGetSymbolAddress((void**)&att, g_att);
    cudaGetSymbolAddress((void**)&h2,  g_h2);
    cudaGetSymbolAddress((void**)&ff,  g_ff);
    cudaGetSymbolAddress((void**)&wq,  g_wq);
    cudaGetSymbolAddress((void**)&wp,  g_wp);
    cudaGetSymbolAddress((void**)&wf,  g_wf);
    cudaGetSymbolAddress((void**)&wo,  g_wo);

    cudaFuncSetAttribute(attn_kernel, cudaFuncAttributeMaxDynamicSharedMemorySize, FLASH_SMEM);
    cudaFuncSetAttribute(gemm_mma_kernel<4>, cudaFuncAttributeMaxDynamicSharedMemorySize, GEMM_SMEM);
    cudaFuncSetAttribute(gemm_mma_kernel<2>, cudaFuncAttributeMaxDynamicSharedMemorySize, GEMM_SMEM);
    cudaFuncSetAttribute(gemm_mma64_kernel<1>, cudaFuncAttributeMaxDynamicSharedMemorySize, GEMM64_SMEM);
    cudaFuncSetAttribute(gemm_mma64_kernel<3>, cudaFuncAttributeMaxDynamicSharedMemorySize, GEMM64_SMEM);

    // 1) prep: LN1 + attnw convert only (critical path)
    prep_kernel<<<2048 + 768, 256>>>(prev, ln1g, ln1b, h1, attnw, wq);
    // 2) qkv = h1 @ c_attn + b (fp16)
    gemm_mma_kernel<4><<<dim3(24, 16), 256, GEMM_SMEM>>>(h1, wq, attnb,
        nullptr, qkv, ROWS, 3*DMODEL, DMODEL, nullptr, nullptr, nullptr);
    // 3) fused flash + memattn + ride-along wconv (wp/wf/wo)
    attn_kernel<<<512 + 2048 + 2304, 128, FLASH_SMEM>>>(qkv, memkv, mem, att,
        cprw, wp, fcw, wf, pw, wo);
    // 4) hid = (1-g)*(att@c_proj+b) + g*mem + prev
    gemm_mma64_kernel<1><<<dim3(8, 32), 128, GEMM64_SMEM>>>(att, wp, cprb,
        hid, nullptr, ROWS, DMODEL, DMODEL, mem, prev, gval);
    // 5) LN2 -> h2
    prep_kernel<<<2048, 256>>>(hid, ln2g, ln2b, h2, nullptr, nullptr);
    // 6) ff = gelu(h2 @ fc + b) -> fp16
    gemm_mma_kernel<2><<<dim3(32, 16), 256, GEMM_SMEM>>>(h2, wf, fcb,
        nullptr, ff, ROWS, 4*DMODEL, DMODEL, nullptr, nullptr, nullptr);
    // 7) out = ff @ proj + b + hid
    gemm_mma64_kernel<3><<<dim3(8, 32), 128, GEMM64_SMEM>>>(ff, wo, pb,
        out, nullptr, ROWS, DMODEL, 4*DMODEL, hid, nullptr, nullptr);
}

// round 17
// speedup vs baseline: 1.1182x; 1.0042x over previous
#include <cuda_runtime.h>
#include <cuda_fp16.h>
#include <cstdint>

#define BS_    2
#define SEQ    1024
#define DMODEL 1024
#define NH     16
#define HD     64
#define MM     32
#define ROWS   (BS_*SEQ)

// ---------------- scratch (device globals) ----------------
__device__ __half g_qkv[ROWS*3*DMODEL];
__device__ __half g_mem[ROWS*DMODEL];
__device__ __half g_hid[ROWS*DMODEL];
__device__ __half g_h1 [ROWS*DMODEL];
__device__ __half g_att[ROWS*DMODEL];
__device__ __half g_h2 [ROWS*DMODEL];
__device__ __half g_ff [ROWS*4*DMODEL];
__device__ __half g_wq[DMODEL*3*DMODEL];
__device__ __half g_wp[DMODEL*DMODEL];
__device__ __half g_wf[DMODEL*4*DMODEL];
__device__ __half g_wo[4*DMODEL*DMODEL];

// ---------------- helpers ----------------
__device__ __forceinline__ uint32_t smem_to_u32(const void* p) {
    uint32_t a;
    asm("{ .reg .u64 t; cvta.to.shared.u64 t, %1; cvt.u32.u64 %0, t; }" : "=r"(a) : "l"(p));
    return a;
}
__device__ __forceinline__ void cp16(uint32_t s, const void* g) {
    asm volatile("cp.async.cg.shared.global [%0], [%1], 16;" :: "r"(s), "l"(g));
}
#define CP_COMMIT() asm volatile("cp.async.commit_group;" ::: "memory")
#define CP_WAIT1()  asm volatile("cp.async.wait_group 1;" ::: "memory")
#define CP_WAIT0()  asm volatile("cp.async.wait_group 0;" ::: "memory")

__device__ __forceinline__ void ldsm4(uint32_t* r, uint32_t addr) {
    asm volatile("ldmatrix.sync.aligned.m8n8.x4.shared.b16 {%0,%1,%2,%3}, [%4];"
        : "=r"(r[0]), "=r"(r[1]), "=r"(r[2]), "=r"(r[3]) : "r"(addr));
}
__device__ __forceinline__ void ldsm2(uint32_t* r, uint32_t addr) {
    asm volatile("ldmatrix.sync.aligned.m8n8.x2.shared.b16 {%0,%1}, [%2];"
        : "=r"(r[0]), "=r"(r[1]) : "r"(addr));
}
__device__ __forceinline__ void ldsm2t(uint32_t* r, uint32_t addr) {
    asm volatile("ldmatrix.sync.aligned.m8n8.x2.trans.shared.b16 {%0,%1}, [%2];"
        : "=r"(r[0]), "=r"(r[1]) : "r"(addr));
}
__device__ __forceinline__ void mma16816(float* d, const uint32_t* a, const uint32_t* b) {
    asm volatile(
      "mma.sync.aligned.m16n8k16.row.col.f32.f16.f16.f32 "
      "{%0,%1,%2,%3}, {%4,%5,%6,%7}, {%8,%9}, {%0,%1,%2,%3};"
      : "+f"(d[0]), "+f"(d[1]), "+f"(d[2]), "+f"(d[3])
      : "r"(a[0]), "r"(a[1]), "r"(a[2]), "r"(a[3]), "r"(b[0]), "r"(b[1]));
}

__device__ __forceinline__ float gelu_new(float x) {
    float x3 = x * x * x;
    float t  = tanhf(0.7978845608028654f * (x + 0.044715f * x3));
    return 0.5f * x * (1.f + t);
}
__device__ __forceinline__ uint32_t pack_h2(float x, float y) {
    __half2 t = __floats2half2_rn(x, y);
    return *reinterpret_cast<uint32_t*>(&t);
}

// ---------------- weight convert bodies ----------------
__device__ void wconv_body(float* shm,
    const float* __restrict__ W, __half* __restrict__ hi,
    int K, int N, int bx, int by)
{
    float (*s)[33] = (float(*)[33])shm;
    const int tx = threadIdx.x & 31, ty = threadIdx.x >> 5;
    const int n0 = bx * 32, k0 = by * 32;
    #pragma unroll
    for (int i = 0; i < 4; i++)
        s[ty + 8*i][tx] = W[(size_t)(k0 + ty + 8*i) * N + n0 + tx];
    __syncthreads();
    #pragma unroll
    for (int i = 0; i < 4; i++) {
        int n = ty + 8*i;
        hi[(size_t)(n0 + n) * K + k0 + tx] = __float2half(s[tx][n]);
    }
    __syncthreads();
}
__device__ void wconv4_body(float* shm,
    const float* __restrict__ W, __half* __restrict__ hi,
    int K, int N, int bxg, int by)
{
    #pragma unroll
    for (int t = 0; t < 4; t++)
        wconv_body(shm, W, hi, K, N, bxg * 4 + t, by);
}

__device__ void wconv_body128(float* shm,
    const float* __restrict__ W, __half* __restrict__ hi,
    int K, int N, int bx, int by)
{
    float (*s)[33] = (float(*)[33])shm;
    const int tx = threadIdx.x & 31, ty = threadIdx.x >> 5;
    const int n0 = bx * 32, k0 = by * 32;
    #pragma unroll
    for (int i = 0; i < 8; i++)
        s[ty + 4*i][tx] = W[(size_t)(k0 + ty + 4*i) * N + n0 + tx];
    __syncthreads();
    #pragma unroll
    for (int i = 0; i < 8; i++) {
        int n = ty + 4*i;
        hi[(size_t)(n0 + n) * K + k0 + tx] = __float2half(s[tx][n]);
    }
    __syncthreads();
}
__device__ void wconv4_body128(float* shm,
    const float* __restrict__ W, __half* __restrict__ hi,
    int K, int N, int bxg, int by)
{
    #pragma unroll
    for (int t = 0; t < 4; t++)
        wconv_body128(shm, W, hi, K, N, bxg * 4 + t, by);
}

// LN over f32 input (LN1)
__device__ void ln_body(float* shm, int row,
    const float* __restrict__ x, const float* __restrict__ g,
    const float* __restrict__ b, __half* __restrict__ y)
{
    const int tid = threadIdx.x;
    float* rs = shm; float* rs2 = shm + 8;
    const float* xr = x + (size_t)row * DMODEL;
    float4 v = *(const float4*)(xr + tid * 4);
    float s  = v.x + v.y + v.z + v.w;
    float s2 = v.x*v.x + v.y*v.y + v.z*v.z + v.w*v.w;
    #pragma unroll
    for (int o = 16; o; o >>= 1) {
        s  += __shfl_xor_sync(0xffffffffu, s,  o);
        s2 += __shfl_xor_sync(0xffffffffu, s2, o);
    }
    const int w = tid >> 5, l = tid & 31;
    if (!l) { rs[w] = s; rs2[w] = s2; }
    __syncthreads();
    s = 0.f; s2 = 0.f;
    #pragma unroll
    for (int i = 0; i < 8; i++) { s += rs[i]; s2 += rs2[i]; }
    const float mean = s * (1.f / DMODEL);
    const float var  = s2 * (1.f / DMODEL) - mean * mean;
    const float rstd = rsqrtf(var + 1e-5f);
    const int c = tid * 4;
    float4 gg = *(const float4*)(g + c);
    float4 bb = *(const float4*)(b + c);
    float4 o;
    o.x = (v.x - mean) * rstd * gg.x + bb.x;
    o.y = (v.y - mean) * rstd * gg.y + bb.y;
    o.z = (v.z - mean) * rstd * gg.z + bb.z;
    o.w = (v.w - mean) * rstd * gg.w + bb.w;
    uint2 hh;
    hh.x = pack_h2(o.x, o.y); hh.y = pack_h2(o.z, o.w);
    *(uint2*)(y + (size_t)row * DMODEL + c) = hh;
}

// LN over fp16 input (LN2 on hid)
__device__ void ln_body_h(float* shm, int row,
    const __half* __restrict__ x, const float* __restrict__ g,
    const float* __restrict__ b, __half* __restrict__ y)
{
    const int tid = threadIdx.x;
    float* rs = shm; float* rs2 = shm + 8;
    const __half* xr = x + (size_t)row * DMODEL;
    uint2 raw = *(const uint2*)(xr + tid * 4);
    __half2 p0 = *(__half2*)&raw.x, p1 = *(__half2*)&raw.y;
    float4 v;
    v.x = __low2float(p0); v.y = __high2float(p0);
    v.z = __low2float(p1); v.w = __high2float(p1);
    float s  = v.x + v.y + v.z + v.w;
    float s2 = v.x*v.x + v.y*v.y + v.z*v.z + v.w*v.w;
    #pragma unroll
    for (int o = 16; o; o >>= 1) {
        s  += __shfl_xor_sync(0xffffffffu, s,  o);
        s2 += __shfl_xor_sync(0xffffffffu, s2, o);
    }
    const int w = tid >> 5, l = tid & 31;
    if (!l) { rs[w] = s; rs2[w] = s2; }
    __syncthreads();
    s = 0.f; s2 = 0.f;
    #pragma unroll
    for (int i = 0; i < 8; i++) { s += rs[i]; s2 += rs2[i]; }
    const float mean = s * (1.f / DMODEL);
    const float var  = s2 * (1.f / DMODEL) - mean * mean;
    const float rstd = rsqrtf(var + 1e-5f);
    const int c = tid * 4;
    float4 gg = *(const float4*)(g + c);
    float4 bb = *(const float4*)(b + c);
    float4 o;
    o.x = (v.x - mean) * rstd * gg.x + bb.x;
    o.y = (v.y - mean) * rstd * gg.y + bb.y;
    o.z = (v.z - mean) * rstd * gg.z + bb.z;
    o.w = (v.w - mean) * rstd * gg.w + bb.w;
    uint2 hh;
    hh.x = pack_h2(o.x, o.y); hh.y = pack_h2(o.z, o.w);
    *(uint2*)(y + (size_t)row * DMODEL + c) = hh;
}

// prep: LN1 (2048) + attnw wconv4 (768)
__global__ void __launch_bounds__(256) prep_kernel(
    const float* x, const float* lng, const float* lnb, __half* y,
    const float* attnw, __half* wq)
{
    __shared__ float shm[32*33];
    int idx = blockIdx.x;
    if (idx < 2048) { ln_body(shm, idx, x, lng, lnb, y); return; }
    idx -= 2048;
    wconv4_body(shm, attnw, wq, 1024, 3072, idx % 24, idx / 24);
}

// LN2 kernel (fp16 input)
__global__ void __launch_bounds__(256) ln2_kernel(
    const __half* x, const float* lng, const float* lnb, __half* y)
{
    __shared__ float shm[32*33];
    ln_body_h(shm, blockIdx.x, x, lng, lnb, y);
}

// ---------------- epilogue (shared) -----------------------------------------
// EPI 2: gelu -> fp16 | 4: -> fp16 | 5: gated(g, half mem, f32 prev) -> fp16 hid
// EPI 6: +bias + half hid -> f32 out
template<int EPI>
__device__ __forceinline__ void gemm_epilogue_elem(
    float v0, float v1, const float2 bb, size_t o,
    float* Cf, __half* Ch,
    const __half* auxh, const float* auxf, float g)
{
    v0 += bb.x; v1 += bb.y;
    if (EPI == 5) {
        __half2 mh = *(const __half2*)(auxh + o);
        float2 pf = *(const float2*)(auxf + o);
        v0 = (1.f - g) * v0 + g * __low2float(mh)  + pf.x;
        v1 = (1.f - g) * v1 + g * __high2float(mh) + pf.y;
        *(uint32_t*)(Ch + o) = pack_h2(v0, v1);
    } else if (EPI == 6) {
        __half2 hh = *(const __half2*)(auxh + o);
        v0 += __low2float(hh); v1 += __high2float(hh);
        *(float2*)(Cf + o) = make_float2(v0, v1);
    } else if (EPI == 2) {
        v0 = gelu_new(v0); v1 = gelu_new(v1);
        *(uint32_t*)(Ch + o) = pack_h2(v0, v1);
    } else {  // EPI == 4
        *(uint32_t*)(Ch + o) = pack_h2(v0, v1);
    }
}

// ---------------- GEMM 128x128 tile, fp16, K-chunk 64 ------------------------
#define AB_     8192
#define GSTAGE  (4*AB_)                 // 32768
#define GEMM_SMEM (3*GSTAGE)            // 98304

template<int EPI>
__global__ void __launch_bounds__(256, 2) gemm_mma_kernel(
    const __half* __restrict__ A, const __half* __restrict__ B,
    const float* __restrict__ bias,
    float* __restrict__ Cf, __half* __restrict__ Ch,
    int M, int N, int K,
    const __half* __restrict__ auxh, const float* __restrict__ auxf,
    const float* __restrict__ gp)
{
    extern __shared__ char smp[];
    const uint32_t sb = smem_to_u32(smp);
    const int tid = threadIdx.x;
    const int wid = tid >> 5, lane = tid & 31;
    const int wm = wid & 1, wn = wid >> 1;
    const int bm = blockIdx.y, bn = blockIdx.x;
    const int NC = K >> 6;

    const size_t Abase = (size_t)bm * 128 * K;
    const size_t Bbase = (size_t)bn * 128 * K;

    float acc[4][4][4];
    #pragma unroll
    for (int i = 0; i < 4; i++)
        #pragma unroll
        for (int j = 0; j < 4; j++)
            #pragma unroll
            for (int x = 0; x < 4; x++) acc[i][j][x] = 0.f;

    const int crow = tid >> 2;
    const int cq   = tid & 3;
    const uint32_t so0 = (uint32_t)(crow * 64 + ((cq ^ (crow & 3)) << 4));
    const uint32_t so1 = so0 + 64 * 64;

    auto issue = [&](int buf, int kt) {
        const int k0 = kt << 6;
        const uint32_t sbase = sb + buf * GSTAGE;
        const size_t g0 = (size_t)crow * K + k0 + cq * 8;
        const size_t g1 = g0 + (size_t)64 * K;
        #pragma unroll
        for (int sl = 0; sl < 2; sl++) {
            cp16(sbase + sl*AB_ + so0,          A + Abase + g0 + sl*32);
            cp16(sbase + sl*AB_ + so1,          A + Abase + g1 + sl*32);
            cp16(sbase + (2+sl)*AB_ + so0,      B + Bbase + g0 + sl*32);
            cp16(sbase + (2+sl)*AB_ + so1,      B + Bbase + g1 + sl*32);
        }
    };

    issue(0, 0); CP_COMMIT();
    issue(1, 1); CP_COMMIT();

    const uint32_t rowA = (uint32_t)(wm * 64 + (lane & 15));
    const uint32_t qa   = (uint32_t)(lane >> 4);
    const uint32_t r3a  = rowA & 3;
    const uint32_t aBase = rowA * 64;
    const uint32_t rowB = (uint32_t)(wn * 32 + (lane & 7));
    const uint32_t qb   = (uint32_t)((lane >> 3) & 1);
    const uint32_t r3b  = rowB & 3;
    const uint32_t bBase = rowB * 64;

    int buf = 0;
    for (int c = 0; c < NC; c++) {
        CP_WAIT1();
        __syncthreads();
        if (c + 2 < NC) { int nb = buf + 2; if (nb >= 3) nb -= 3; issue(nb, c + 2); }
        CP_COMMIT();

        const uint32_t s0 = sb + buf * GSTAGE;
        #pragma unroll
        for (int sl = 0; sl < 2; sl++) {
            const uint32_t sA = s0 + sl*AB_;
            const uint32_t sB = s0 + (2+sl)*AB_;
            #pragma unroll
            for (int ks = 0; ks < 2; ks++) {
                uint32_t bfr[4][2];
                const uint32_t qpb = ((qb + 2*ks) ^ r3b) << 4;
                #pragma unroll
                for (int nt = 0; nt < 4; nt++)
                    ldsm2(bfr[nt], sB + bBase + (uint32_t)(nt * 512) + qpb);
                const uint32_t qpa = ((qa + 2*ks) ^ r3a) << 4;
                #pragma unroll
                for (int mt = 0; mt < 4; mt++) {
                    uint32_t a[4];
                    ldsm4(a, sA + aBase + (uint32_t)(mt * 1024) + qpa);
                    #pragma unroll
                    for (int nt = 0; nt < 4; nt++) mma16816(acc[mt][nt], a, bfr[nt]);
                }
            }
        }
        buf++; if (buf >= 3) buf = 0;
    }

    const int r = lane >> 2, q = lane & 3;
    const float g = (EPI == 5) ? *gp : 0.f;
    #pragma unroll
    for (int mt = 0; mt < 4; mt++) {
        #pragma unroll
        for (int nt = 0; nt < 4; nt++) {
            const int col = bn * 128 + wn * 32 + nt * 8 + q * 2;
            const float2 bb = *(const float2*)(bias + col);
            #pragma unroll
            for (int hh = 0; hh < 2; hh++) {
                const int row = bm * 128 + wm * 64 + mt * 16 + r + hh * 8;
                gemm_epilogue_elem<EPI>(acc[mt][nt][hh*2], acc[mt][nt][hh*2+1], bb,
                    (size_t)row * N + col, Cf, Ch, auxh, auxf, g);
            }
        }
    }
}

// ---------------- GEMM 64x128 tile, fp16, K-chunk 64 -------------------------
#define A64_      4096
#define B64_      8192
#define GSTAGE64  (2*A64_ + 2*B64_)     // 24576
#define GEMM64_SMEM (3*GSTAGE64)        // 73728

template<int EPI>
__global__ void __launch_bounds__(128, 3) gemm_mma64_kernel(
    const __half* __restrict__ A, const __half* __restrict__ B,
    const float* __restrict__ bias,
    float* __restrict__ Cf, __half* __restrict__ Ch,
    int M, int N, int K,
    const __half* __restrict__ auxh, const float* __restrict__ auxf,
    const float* __restrict__ gp)
{
    extern __shared__ char smp[];
    const uint32_t sb = smem_to_u32(smp);
    const int tid = threadIdx.x;
    const int wn = tid >> 5, lane = tid & 31;
    const int bm = blockIdx.y, bn = blockIdx.x;
    const int NC = K >> 6;

    const size_t Abase = (size_t)bm * 64 * K;
    const size_t Bbase = (size_t)bn * 128 * K;

    float acc[4][4][4];
    #pragma unroll
    for (int i = 0; i < 4; i++)
        #pragma unroll
        for (int j = 0; j < 4; j++)
            #pragma unroll
            for (int x = 0; x < 4; x++) acc[i][j][x] = 0.f;

    const int crow = tid >> 2;
    const int cq   = tid & 3;
    const uint32_t soA = (uint32_t)(crow * 64 + ((cq ^ (crow & 3)) << 4));

    auto issue = [&](int buf, int kt) {
        const int k0 = kt << 6;
        const uint32_t sbase = sb + buf * GSTAGE64;
        const size_t gc = (size_t)crow * K + k0 + cq * 8;
        #pragma unroll
        for (int sl = 0; sl < 2; sl++) {
            cp16(sbase + sl*A64_ + soA,        A + Abase + gc + sl*32);
            cp16(sbase + sl*A64_ + soA + 2048, A + Abase + gc + sl*32 + (size_t)32 * K);
            #pragma unroll
            for (int j = 0; j < 4; j++)
                cp16(sbase + 2*A64_ + sl*B64_ + soA + j*2048,
                     B + Bbase + gc + sl*32 + (size_t)(32 * j) * K);
        }
    };

    issue(0, 0); CP_COMMIT();
    issue(1, 1); CP_COMMIT();

    const uint32_t rowA = (uint32_t)(lane & 15);
    const uint32_t qa   = (uint32_t)(lane >> 4);
    const uint32_t r3a  = rowA & 3;
    const uint32_t aBase = rowA * 64;
    const uint32_t rowB = (uint32_t)(wn * 32 + (lane & 7));
    const uint32_t qb   = (uint32_t)((lane >> 3) & 1);
    const uint32_t r3b  = rowB & 3;
    const uint32_t bBase = rowB * 64;

    int buf = 0;
    for (int c = 0; c < NC; c++) {
        CP_WAIT1();
        __syncthreads();
        if (c + 2 < NC) { int nb = buf + 2; if (nb >= 3) nb -= 3; issue(nb, c + 2); }
        CP_COMMIT();

        const uint32_t s0 = sb + buf * GSTAGE64;
        #pragma unroll
        for (int sl = 0; sl < 2; sl++) {
            const uint32_t sA = s0 + sl*A64_;
            const uint32_t sB = s0 + 2*A64_ + sl*B64_;
            #pragma unroll
            for (int ks = 0; ks < 2; ks++) {
                uint32_t bfr[4][2];
                const uint32_t qpb = ((qb + 2*ks) ^ r3b) << 4;
                #pragma unroll
                for (int nt = 0; nt < 4; nt++)
                    ldsm2(bfr[nt], sB + bBase + (uint32_t)(nt * 512) + qpb);
                const uint32_t qpa = ((qa + 2*ks) ^ r3a) << 4;
                #pragma unroll
                for (int mt = 0; mt < 4; mt++) {
                    uint32_t a[4];
                    ldsm4(a, sA + aBase + (uint32_t)(mt * 1024) + qpa);
                    #pragma unroll
                    for (int nt = 0; nt < 4; nt++) mma16816(acc[mt][nt], a, bfr[nt]);
                }
            }
        }
        buf++; if (buf >= 3) buf = 0;
    }

    const int r = lane >> 2, q = lane & 3;
    const float g = (EPI == 5) ? *gp : 0.f;
    #pragma unroll
    for (int mt = 0; mt < 4; mt++) {
        #pragma unroll
        for (int nt = 0; nt < 4; nt++) {
            const int col = bn * 128 + wn * 32 + nt * 8 + q * 2;
            const float2 bb = *(const float2*)(bias + col);
            #pragma unroll
            for (int hh = 0; hh < 2; hh++) {
                const int row = bm * 64 + mt * 16 + r + hh * 8;
                gemm_epilogue_elem<EPI>(acc[mt][nt][hh*2], acc[mt][nt][hh*2+1], bb,
                    (size_t)row * N + col, Cf, Ch, auxh, auxf, g);
            }
        }
    }
}

// ---------------- fused attention + ride-along wconv (128 threads) ----------
#define FROW 144
#define KVBUF (2*9216)
#define FLASH_SMEM (9216 + 2*KVBUF)

__device__ void memattn_body(const __half* __restrict__ qkv,
                             const float* __restrict__ mkv,
                             __half* __restrict__ outm, int row)
{
    const int tid = threadIdx.x;
    const int h = tid >> 3, t8 = tid & 7;
    __shared__ float sc[NH * MM];
    const int co = h * 64 + t8 * 8;
    uint4 qraw = *(const uint4*)(qkv + (size_t)row * 3072 + co);
    float qv[8];
    {
        __half2* qh = (__half2*)&qraw;
        #pragma unroll
        for (int i = 0; i < 4; i++) {
            qv[2*i]   = __low2float(qh[i])  * 0.125f;
            qv[2*i+1] = __high2float(qh[i]) * 0.125f;
        }
    }
    const float* kbase = mkv + (size_t)row * MM * 2 * DMODEL;
    #pragma unroll 4
    for (int m = 0; m < MM; m++) {
        const float* kp = kbase + (size_t)m * 2 * DMODEL + co;
        float4 k0 = *(const float4*)(kp);
        float4 k1 = *(const float4*)(kp + 4);
        float d = qv[0]*k0.x + qv[1]*k0.y + qv[2]*k0.z + qv[3]*k0.w
                + qv[4]*k1.x + qv[5]*k1.y + qv[6]*k1.z + qv[7]*k1.w;
        #pragma unroll
        for (int o = 4; o; o >>= 1) d += __shfl_xor_sync(0xffffffffu, d, o);
        if (t8 == 0) sc[h * MM + m] = d;
    }
    __syncthreads();
    if (tid < NH) {
        float mx = -1e30f;
        #pragma unroll
        for (int m = 0; m < MM; m++) mx = fmaxf(mx, sc[tid * MM + m]);
        float s = 0.f;
        #pragma unroll
        for (int m = 0; m < MM; m++) {
            float e = __expf(sc[tid * MM + m] - mx);
            sc[tid * MM + m] = e; s += e;
        }
        float inv = 1.f / s;
        #pragma unroll
        for (int m = 0; m < MM; m++) sc[tid * MM + m] *= inv;
    }
    __syncthreads();
    float a0 = 0.f, a1 = 0.f, a2 = 0.f, a3 = 0.f, a4 = 0.f, a5 = 0.f, a6 = 0.f, a7 = 0.f;
    #pragma unroll 4
    for (int m = 0; m < MM; m++) {
        float w = sc[h * MM + m];
        const float* vp = kbase + (size_t)m * 2 * DMODEL + DMODEL + co;
        float4 v0 = *(const float4*)(vp);
        float4 v1 = *(const float4*)(vp + 4);
        a0 += w*v0.x; a1 += w*v0.y; a2 += w*v0.z; a3 += w*v0.w;
        a4 += w*v1.x; a5 += w*v1.y; a6 += w*v1.z; a7 += w*v1.w;
    }
    uint4 packed;
    packed.x = pack_h2(a0, a1); packed.y = pack_h2(a2, a3);
    packed.z = pack_h2(a4, a5); packed.w = pack_h2(a6, a7);
    *(uint4*)(outm + (size_t)row * DMODEL + co) = packed;
}

__device__ void flash_body(const __half* __restrict__ qkv,
                           __half* __restrict__ outO,
                           char* sm, int fb)
{
    const int tid = threadIdx.x, lane = tid & 31, wm = tid >> 5;
    const int qt = 15 - (fb & 15);
    const int bhh = fb >> 4, b = bhh >> 4, h = bhh & 15;
    const int qbase = qt * 64;
    const size_t srow = (size_t)b * SEQ;

    const uint32_t QA = smem_to_u32(sm);

    const int lrow = tid >> 1;
    const int lh   = (tid & 1) * 32;

    auto issue_kv = [&](int bufi, int kt) {
        const __half* gk = qkv + (srow + kt*64 + lrow) * 3072 + 1024 + h * 64 + lh;
        const uint32_t kd = QA + 9216 + (uint32_t)(bufi * KVBUF) + (uint32_t)(lrow * FROW + lh * 2);
        cp16(kd,      gk);
        cp16(kd + 16, gk + 8);
        cp16(kd + 32, gk + 16);
        cp16(kd + 48, gk + 24);
        const uint32_t vd = kd + 9216;
        cp16(vd,      gk + 1024);
        cp16(vd + 16, gk + 1024 + 8);
        cp16(vd + 32, gk + 1024 + 16);
        cp16(vd + 48, gk + 1024 + 24);
    };

    {
        const __half* gq = qkv + (srow + qbase + lrow) * 3072 + h * 64 + lh;
        const uint32_t qd = QA + (uint32_t)(lrow * FROW + lh * 2);
        cp16(qd,      gq);
        cp16(qd + 16, gq + 8);
        cp16(qd + 32, gq + 16);
        cp16(qd + 48, gq + 24);
    }
    issue_kv(0, 0);
    CP_COMMIT();

    const int r = lane >> 2, q = lane & 3;
    float m0 = -1e30f, m1 = -1e30f, l0 = 0.f, l1 = 0.f;
    float o[8][4];
    #pragma unroll
    for (int i = 0; i < 8; i++) o[i][0]=o[i][1]=o[i][2]=o[i][3]=0.f;

    const uint32_t qaddr0 = QA + (uint32_t)((wm*16 + (lane & 15)) * FROW + ((lane >> 4) & 1) * 16);
    const uint32_t kOff = (uint32_t)((lane & 7) * FROW + ((lane >> 3) & 1) * 16);
    const uint32_t vOff = (uint32_t)((lane & 15) * FROW);

    for (int kt = 0; kt <= qt; kt++) {
        CP_WAIT0();
        __syncthreads();
        if (kt < qt) issue_kv((kt + 1) & 1, kt + 1);
        CP_COMMIT();

        const uint32_t kvb = QA + 9216 + (uint32_t)((kt & 1) * KVBUF);
        const uint32_t kaddr0 = kvb + kOff;
        const uint32_t vaddr0 = kvb + 9216 + vOff;

        float s[8][4];
        #pragma unroll
        for (int nt = 0; nt < 8; nt++) s[nt][0]=s[nt][1]=s[nt][2]=s[nt][3]=0.f;
        #pragma unroll
        for (int ks = 0; ks < 4; ks++) {
            uint32_t aQ[4];
            ldsm4(aQ, qaddr0 + ks*32);
            uint32_t bK[8][2];
            #pragma unroll
            for (int nt = 0; nt < 8; nt++)
                ldsm2(bK[nt], kaddr0 + (uint32_t)(nt * 8 * FROW + ks * 32));
            #pragma unroll
            for (int nt = 0; nt < 8; nt++) mma16816(s[nt], aQ, bK[nt]);
        }
        #pragma unroll
        for (int nt = 0; nt < 8; nt++) {
            s[nt][0] *= 0.125f; s[nt][1] *= 0.125f;
            s[nt][2] *= 0.125f; s[nt][3] *= 0.125f;
        }

        if (kt == qt) {
            const int r0 = wm*16 + r;
            #pragma unroll
            for (int nt = 0; nt < 8; nt++) {
                const int cb = nt*8 + q*2;
                if (cb     > r0)     s[nt][0] = -1e30f;
                if (cb + 1 > r0)     s[nt][1] = -1e30f;
                if (cb     > r0 + 8) s[nt][2] = -1e30f;
                if (cb + 1 > r0 + 8) s[nt][3] = -1e30f;
            }
        }

        float mx0 = -1e30f, mx1 = -1e30f;
        #pragma unroll
        for (int nt = 0; nt < 8; nt++) {
            mx0 = fmaxf(mx0, fmaxf(s[nt][0], s[nt][1]));
            mx1 = fmaxf(mx1, fmaxf(s[nt][2], s[nt][3]));
        }
        mx0 = fmaxf(mx0, __shfl_xor_sync(0xffffffffu, mx0, 1));
        mx0 = fmaxf(mx0, __shfl_xor_sync(0xffffffffu, mx0, 2));
        mx1 = fmaxf(mx1, __shfl_xor_sync(0xffffffffu, mx1, 1));
        mx1 = fmaxf(mx1, __shfl_xor_sync(0xffffffffu, mx1, 2));
        const float mn0 = fmaxf(m0, mx0);
        const float mn1 = fmaxf(m1, mx1);
        const float al0 = __expf(m0 - mn0), al1 = __expf(m1 - mn1);
        float sum0 = 0.f, sum1 = 0.f;
        #pragma unroll
        for (int nt = 0; nt < 8; nt++) {
            s[nt][0] = __expf(s[nt][0] - mn0);
            s[nt][1] = __expf(s[nt][1] - mn0);
            s[nt][2] = __expf(s[nt][2] - mn1);
            s[nt][3] = __expf(s[nt][3] - mn1);
            sum0 += s[nt][0] + s[nt][1];
            sum1 += s[nt][2] + s[nt][3];
        }
        sum0 += __shfl_xor_sync(0xffffffffu, sum0, 1);
        sum0 += __shfl_xor_sync(0xffffffffu, sum0, 2);
        sum1 += __shfl_xor_sync(0xffffffffu, sum1, 1);
        sum1 += __shfl_xor_sync(0xffffffffu, sum1, 2);
        l0 = al0 * l0 + sum0;
        l1 = al1 * l1 + sum1;
        m0 = mn0; m1 = mn1;
        #pragma unroll
        for (int i = 0; i < 8; i++) {
            o[i][0] *= al0; o[i][1] *= al0; o[i][2] *= al1; o[i][3] *= al1;
        }

        uint32_t aP[4][4];
        #pragma unroll
        for (int ks = 0; ks < 4; ks++) {
            const int n0 = 2*ks, n1 = 2*ks + 1;
            aP[ks][0] = pack_h2(s[n0][0], s[n0][1]);
            aP[ks][1] = pack_h2(s[n0][2], s[n0][3]);
            aP[ks][2] = pack_h2(s[n1][0], s[n1][1]);
            aP[ks][3] = pack_h2(s[n1][2], s[n1][3]);
        }
        #pragma unroll
        for (int ks = 0; ks < 4; ks++) {
            #pragma unroll
            for (int gq4 = 0; gq4 < 2; gq4++) {
                uint32_t bV[4][2];
                #pragma unroll
                for (int j = 0; j < 4; j++)
                    ldsm2t(bV[j], vaddr0 + (uint32_t)(ks * 16 * FROW + (gq4*4 + j) * 16));
                #pragma unroll
                for (int j = 0; j < 4; j++) mma16816(o[gq4*4+j], aP[ks], bV[j]);
            }
        }
    }

    const float i0 = 1.f / l0, i1 = 1.f / l1;
    #pragma unroll
    for (int ntv = 0; ntv < 8; ntv++) {
        const int rg = wm*16 + r, cg = ntv*8 + q*2;
        const size_t o0 = (srow + qbase + rg) * (size_t)DMODEL + h*64 + cg;
        const size_t o1 = o0 + 8 * DMODEL;
        *(uint32_t*)(outO + o0) = pack_h2(o[ntv][0] * i0, o[ntv][1] * i0);
        *(uint32_t*)(outO + o1) = pack_h2(o[ntv][2] * i1, o[ntv][3] * i1);
    }
}

__global__ void __launch_bounds__(128) attn_kernel(
    const __half* __restrict__ qkv, const float* __restrict__ mkv,
    __half* __restrict__ outm, __half* __restrict__ outO,
    const float* __restrict__ cprw, __half* __restrict__ wp,
    const float* __restrict__ fcw,  __half* __restrict__ wf,
    const float* __restrict__ pw,   __half* __restrict__ wo)
{
    extern __shared__ char sm[];
    int idx = blockIdx.x;
    if (idx < 512) { flash_body(qkv, outO, sm, idx); return; }
    idx -= 512;
    if (idx < 2048) { memattn_body(qkv, mkv, outm, idx); return; }
    idx -= 2048;
    float* shm = (float*)sm;
    if (idx < 256)  { wconv4_body128(shm, cprw, wp, 1024, 1024, idx % 8, idx / 8); return; }
    idx -= 256;
    if (idx < 1024) { wconv4_body128(shm, fcw, wf, 1024, 4096, idx % 32, idx / 32); return; }
    idx -= 1024;
    wconv4_body128(shm, pw, wo, 4096, 1024, idx % 8, idx / 8);
}

// ------------------------------ launcher ------------------------------------
extern "C" void kernel_launch(void* const* d_in, const int* in_sizes, int n_in,
                              void* d_out, int out_size)
{
    (void)in_sizes; (void)n_in; (void)out_size;
    const float* prev  = (const float*)d_in[0];
    const float* memkv = (const float*)d_in[1];
    const float* gval  = (const float*)d_in[2];
    const float* ln1g  = (const float*)d_in[3];
    const float* ln1b  = (const float*)d_in[4];
    const float* attnw = (const float*)d_in[5];
    const float* attnb = (const float*)d_in[6];
    const float* cprw  = (const float*)d_in[7];
    const float* cprb  = (const float*)d_in[8];
    const float* ln2g  = (const float*)d_in[9];
    const float* ln2b  = (const float*)d_in[10];
    const float* fcw   = (const float*)d_in[11];
    const float* fcb   = (const float*)d_in[12];
    const float* pw    = (const float*)d_in[13];
    const float* pb    = (const float*)d_in[14];
    float* out = (float*)d_out;

    __half *qkv, *mem, *hid, *h1, *att, *h2, *ff, *wq, *wp, *wf, *wo;
    cudaGetSymbolAddress((void**)&qkv, g_qkv);
    cudaGetSymbolAddress((void**)&mem, g_mem);
    cudaGetSymbolAddress((void**)&hid, g_hid);
    cudaGetSymbolAddress((void**)&h1,  g_h1);
    cudaGetSymbolAddress((void**)&att, g_att);
    cudaGetSymbolAddress((void**)&h2,  g_h2);
    cudaGetSymbolAddress((void**)&ff,  g_ff);
    cudaGetSymbolAddress((void**)&wq,  g_wq);
    cudaGetSymbolAddress((void**)&wp,  g_wp);
    cudaGetSymbolAddress((void**)&wf,  g_wf);
    cudaGetSymbolAddress((void**)&wo,  g_wo);

    cudaFuncSetAttribute(attn_kernel, cudaFuncAttributeMaxDynamicSharedMemorySize, FLASH_SMEM);
    cudaFuncSetAttribute(gemm_mma_kernel<4>, cudaFuncAttributeMaxDynamicSharedMemorySize, GEMM_SMEM);
    cudaFuncSetAttribute(gemm_mma_kernel<2>, cudaFuncAttributeMaxDynamicSharedMemorySize, GEMM_SMEM);
    cudaFuncSetAttribute(gemm_mma64_kernel<5>, cudaFuncAttributeMaxDynamicSharedMemorySize, GEMM64_SMEM);
    cudaFuncSetAttribute(gemm_mma64_kernel<6>, cudaFuncAttributeMaxDynamicSharedMemorySize, GEMM64_SMEM);

    // 1) prep: LN1 + attnw convert (critical path)
    prep_kernel<<<2048 + 768, 256>>>(prev, ln1g, ln1b, h1, attnw, wq);
    // 2) qkv = h1 @ c_attn + b (fp16)
    gemm_mma_kernel<4><<<dim3(24, 16), 256, GEMM_SMEM>>>(h1, wq, attnb,
        nullptr, qkv, ROWS, 3*DMODEL, DMODEL, nullptr, nullptr, nullptr);
    // 3) fused flash + memattn(->fp16) + ride-along wconv
    attn_kernel<<<512 + 2048 + 2304, 128, FLASH_SMEM>>>(qkv, memkv, mem, att,
        cprw, wp, fcw, wf, pw, wo);
    // 4) hid = (1-g)*(att@c_proj+b) + g*mem + prev  -> fp16
    gemm_mma64_kernel<5><<<dim3(8, 32), 128, GEMM64_SMEM>>>(att, wp, cprb,
        nullptr, hid, ROWS, DMODEL, DMODEL, mem, prev, gval);
    // 5) LN2 (fp16 in) -> h2
    ln2_kernel<<<2048, 256>>>(hid, ln2g, ln2b, h2);
    // 6) ff = gelu(h2 @ fc + b) -> fp16
    gemm_mma_kernel<2><<<dim3(32, 16), 256, GEMM_SMEM>>>(h2, wf, fcb,
        nullptr, ff, ROWS, 4*DMODEL, DMODEL, nullptr, nullptr, nullptr);
    // 7) out = ff @ proj + b + hid(fp16) -> f32
    gemm_mma64_kernel<6><<<dim3(8, 32), 128, GEMM64_SMEM>>>(ff, wo, pb,
        out, nullptr, ROWS, DMODEL, 4*DMODEL, hid, nullptr, nullptr);
}